// round 2
// baseline (speedup 1.0000x reference)
#include <cuda_runtime.h>
#include <math.h>

#define SRC_LEN 400
#define TGT_LEN 100
#define Bsz     32
#define Ed      256
#define Hd      512
#define Vd      32000
#define G3H     1536   // 3*Hd
#define NPART   1000   // logits partials: 125 blocks * 8 warps

// ---------------- scratch (device globals; no allocation allowed) ----------
__device__ float g_gi_enc[(size_t)SRC_LEN * G3H * Bsz];   // [t][j(1536)][b]
__device__ float g_gi_dec[(size_t)TGT_LEN * G3H * Bsz];
__device__ float g_hA[Hd * Bsz];                          // h layout [k][b]
__device__ float g_hB[Hd * Bsz];
__device__ float g_oe[Ed * Bsz];                          // out_emb [e][b]
__device__ float g_pm[NPART * Bsz];
__device__ float g_ps[NPART * Bsz];
__device__ int   g_pi[NPART * Bsz];
__device__ float g_loss;

// ---------------- init: zero h0 and loss accumulator -----------------------
__global__ void init_kernel() {
    int i = blockIdx.x * blockDim.x + threadIdx.x;
    if (i < Hd * Bsz) g_hA[i] = 0.0f;
    if (i == 0) g_loss = 0.0f;
}

// ---------------- gi precompute: gi[t][j][b] = emb[tok[t][b]] . W_ih[j] + b_ih[j]
// grid.x = T, block = 256 (8 warps, 192 j each). dec_mode: tok = t==0 ? SOS : target[t-1]
__global__ void gi_kernel(const int* __restrict__ toks,
                          const float* __restrict__ emb,
                          const float* __restrict__ Wih,
                          const float* __restrict__ bih,
                          int dec_mode) {
    __shared__ float xs[Ed * Bsz];   // x transposed [e][b], 32KB
    __shared__ int   tk[Bsz];
    const int t   = blockIdx.x;
    const int tid = threadIdx.x;

    if (tid < Bsz) {
        int tok;
        if (dec_mode) tok = (t == 0) ? 1 : toks[(t - 1) * Bsz + tid];
        else          tok = toks[t * Bsz + tid];
        tk[tid] = tok;
    }
    __syncthreads();

    // load x: thread (b = tid&31, chunk = tid>>5) covers e in [chunk*32, chunk*32+32)
    {
        const int b = tid & 31, chunk = tid >> 5;
        const float* erow = emb + (size_t)tk[b] * Ed;
        #pragma unroll
        for (int c = 0; c < 8; c++) {
            int e0 = chunk * 32 + c * 4;
            float4 v = *(const float4*)(erow + e0);
            xs[(e0 + 0) * Bsz + b] = v.x;
            xs[(e0 + 1) * Bsz + b] = v.y;
            xs[(e0 + 2) * Bsz + b] = v.z;
            xs[(e0 + 3) * Bsz + b] = v.w;
        }
    }
    __syncthreads();

    const int wid = tid >> 5, lane = tid & 31;
    float* out_t = (dec_mode ? g_gi_dec : g_gi_enc) + (size_t)t * G3H * Bsz;

    for (int jt = 0; jt < 24; jt++) {
        const int j0 = wid * 192 + jt * 8;
        float acc0=0,acc1=0,acc2=0,acc3=0,acc4=0,acc5=0,acc6=0,acc7=0;
        #pragma unroll 2
        for (int e0 = 0; e0 < Ed; e0 += 4) {
            float x0 = xs[(e0 + 0) * Bsz + lane];
            float x1 = xs[(e0 + 1) * Bsz + lane];
            float x2 = xs[(e0 + 2) * Bsz + lane];
            float x3 = xs[(e0 + 3) * Bsz + lane];
            const float* wp = Wih + (size_t)j0 * Ed + e0;
            #pragma unroll
            for (int jj = 0; jj < 8; jj++) {
                float4 w = *(const float4*)(wp + (size_t)jj * Ed);
                float a;
                switch (jj) { case 0: a=acc0; break; case 1: a=acc1; break;
                              case 2: a=acc2; break; case 3: a=acc3; break;
                              case 4: a=acc4; break; case 5: a=acc5; break;
                              case 6: a=acc6; break; default: a=acc7; }
                a = fmaf(w.x, x0, a); a = fmaf(w.y, x1, a);
                a = fmaf(w.z, x2, a); a = fmaf(w.w, x3, a);
                switch (jj) { case 0: acc0=a; break; case 1: acc1=a; break;
                              case 2: acc2=a; break; case 3: acc3=a; break;
                              case 4: acc4=a; break; case 5: acc5=a; break;
                              case 6: acc6=a; break; default: acc7=a; }
            }
        }
        float accs[8] = {acc0,acc1,acc2,acc3,acc4,acc5,acc6,acc7};
        #pragma unroll
        for (int jj = 0; jj < 8; jj++)
            out_t[(size_t)(j0 + jj) * Bsz + lane] = accs[jj] + bih[j0 + jj];
    }
}

// ---------------- GRU recurrent step: h_new = GRUcell(gi_t, h) --------------
// grid 128 blocks x 256 thr. warp w: jloc = w>>1 (0..3), kh = w&1 (k-split x2)
// j = bid*4 + jloc. h layout [k][b]. flip: 0 reads hA writes hB, 1 reverse.
__global__ void hh_kernel(int mode, int t,
                          const float* __restrict__ Whh,
                          const float* __restrict__ bhh,
                          int flip) {
    __shared__ float pr[4][3][32];
    const float* __restrict__ hin  = flip ? g_hB : g_hA;
    float* __restrict__ hout = flip ? g_hA : g_hB;
    const float* __restrict__ gi =
        (mode ? g_gi_dec : g_gi_enc) + (size_t)t * G3H * Bsz;

    const int tid = threadIdx.x;
    const int wid = tid >> 5, lane = tid & 31;
    const int jloc = wid >> 1, kh = wid & 1;
    const int j = blockIdx.x * 4 + jloc;

    const float* wr = Whh + (size_t)(0 * Hd + j) * Hd;
    const float* wz = Whh + (size_t)(1 * Hd + j) * Hd;
    const float* wn = Whh + (size_t)(2 * Hd + j) * Hd;

    float ar = 0.f, az = 0.f, an = 0.f;
    const int kbeg = kh * 256, kend = kbeg + 256;
    #pragma unroll 4
    for (int k0 = kbeg; k0 < kend; k0 += 4) {
        float4 r4 = *(const float4*)(wr + k0);
        float4 z4 = *(const float4*)(wz + k0);
        float4 n4 = *(const float4*)(wn + k0);
        float h0 = hin[(k0 + 0) * Bsz + lane];
        float h1 = hin[(k0 + 1) * Bsz + lane];
        float h2 = hin[(k0 + 2) * Bsz + lane];
        float h3 = hin[(k0 + 3) * Bsz + lane];
        ar = fmaf(r4.x, h0, ar); ar = fmaf(r4.y, h1, ar);
        ar = fmaf(r4.z, h2, ar); ar = fmaf(r4.w, h3, ar);
        az = fmaf(z4.x, h0, az); az = fmaf(z4.y, h1, az);
        az = fmaf(z4.z, h2, az); az = fmaf(z4.w, h3, az);
        an = fmaf(n4.x, h0, an); an = fmaf(n4.y, h1, an);
        an = fmaf(n4.z, h2, an); an = fmaf(n4.w, h3, an);
    }

    if (kh == 1) {
        pr[jloc][0][lane] = ar; pr[jloc][1][lane] = az; pr[jloc][2][lane] = an;
    }
    __syncthreads();
    if (kh == 0) {
        ar += pr[jloc][0][lane]; az += pr[jloc][1][lane]; an += pr[jloc][2][lane];
        float ghr = ar + bhh[j];
        float ghz = az + bhh[Hd + j];
        float ghn = an + bhh[2 * Hd + j];
        float gir = gi[(size_t)(0 * Hd + j) * Bsz + lane];
        float giz = gi[(size_t)(1 * Hd + j) * Bsz + lane];
        float gin = gi[(size_t)(2 * Hd + j) * Bsz + lane];
        float r = 1.0f / (1.0f + expf(-(gir + ghr)));
        float z = 1.0f / (1.0f + expf(-(giz + ghz)));
        float n = tanhf(gin + r * ghn);
        float hold = hin[j * Bsz + lane];
        hout[j * Bsz + lane] = (1.0f - z) * n + z * hold;
    }
}

// ---------------- out_emb[e][b] = h . pre_W[e] + pre_b[e] -------------------
// grid 32 x 256 (8 warps -> e = bid*8+wid). reads h_new = flip ? hA : hB.
__global__ void pre_kernel(const float* __restrict__ preW,
                           const float* __restrict__ preb,
                           int flip) {
    const float* __restrict__ h = flip ? g_hA : g_hB;
    const int tid = threadIdx.x;
    const int wid = tid >> 5, lane = tid & 31;
    const int e = blockIdx.x * 8 + wid;
    const float* wp = preW + (size_t)e * Hd;
    float acc = 0.f;
    #pragma unroll 4
    for (int k0 = 0; k0 < Hd; k0 += 4) {
        float4 w = *(const float4*)(wp + k0);
        acc = fmaf(w.x, h[(k0 + 0) * Bsz + lane], acc);
        acc = fmaf(w.y, h[(k0 + 1) * Bsz + lane], acc);
        acc = fmaf(w.z, h[(k0 + 2) * Bsz + lane], acc);
        acc = fmaf(w.w, h[(k0 + 3) * Bsz + lane], acc);
    }
    g_oe[e * Bsz + lane] = acc + preb[e];
}

// ---------------- logits + online softmax partials --------------------------
// grid 125 x 256. global warp gw handles v in [gw*32, gw*32+32), lanes = batch.
__global__ void logits_kernel(const float* __restrict__ emb,
                              const float* __restrict__ outb) {
    __shared__ float oes[Ed * Bsz];
    const int tid = threadIdx.x;
    for (int i = tid; i < Ed * Bsz; i += 256) oes[i] = g_oe[i];
    __syncthreads();

    const int wid = tid >> 5, lane = tid & 31;
    const int gw = blockIdx.x * 8 + wid;
    const int v0 = gw * 32;

    float m = -INFINITY, s = 0.f;
    int   bi = 0;

    for (int vt = 0; vt < 4; vt++) {
        const int vb = v0 + vt * 8;
        float a0=0,a1=0,a2=0,a3=0,a4=0,a5=0,a6=0,a7=0;
        #pragma unroll 2
        for (int e0 = 0; e0 < Ed; e0 += 4) {
            float x0 = oes[(e0 + 0) * Bsz + lane];
            float x1 = oes[(e0 + 1) * Bsz + lane];
            float x2 = oes[(e0 + 2) * Bsz + lane];
            float x3 = oes[(e0 + 3) * Bsz + lane];
            const float* ep = emb + (size_t)vb * Ed + e0;
            float4 w;
            w = *(const float4*)(ep + 0 * Ed);
            a0=fmaf(w.x,x0,a0); a0=fmaf(w.y,x1,a0); a0=fmaf(w.z,x2,a0); a0=fmaf(w.w,x3,a0);
            w = *(const float4*)(ep + 1 * Ed);
            a1=fmaf(w.x,x0,a1); a1=fmaf(w.y,x1,a1); a1=fmaf(w.z,x2,a1); a1=fmaf(w.w,x3,a1);
            w = *(const float4*)(ep + 2 * Ed);
            a2=fmaf(w.x,x0,a2); a2=fmaf(w.y,x1,a2); a2=fmaf(w.z,x2,a2); a2=fmaf(w.w,x3,a2);
            w = *(const float4*)(ep + 3 * Ed);
            a3=fmaf(w.x,x0,a3); a3=fmaf(w.y,x1,a3); a3=fmaf(w.z,x2,a3); a3=fmaf(w.w,x3,a3);
            w = *(const float4*)(ep + 4 * Ed);
            a4=fmaf(w.x,x0,a4); a4=fmaf(w.y,x1,a4); a4=fmaf(w.z,x2,a4); a4=fmaf(w.w,x3,a4);
            w = *(const float4*)(ep + 5 * Ed);
            a5=fmaf(w.x,x0,a5); a5=fmaf(w.y,x1,a5); a5=fmaf(w.z,x2,a5); a5=fmaf(w.w,x3,a5);
            w = *(const float4*)(ep + 6 * Ed);
            a6=fmaf(w.x,x0,a6); a6=fmaf(w.y,x1,a6); a6=fmaf(w.z,x2,a6); a6=fmaf(w.w,x3,a6);
            w = *(const float4*)(ep + 7 * Ed);
            a7=fmaf(w.x,x0,a7); a7=fmaf(w.y,x1,a7); a7=fmaf(w.z,x2,a7); a7=fmaf(w.w,x3,a7);
        }
        float accs[8] = {a0,a1,a2,a3,a4,a5,a6,a7};
        #pragma unroll
        for (int vv = 0; vv < 8; vv++) {
            float l = accs[vv] + outb[vb + vv];
            if (l > m) { s = s * __expf(m - l) + 1.0f; m = l; bi = vb + vv; }
            else       { s += __expf(l - m); }
        }
    }
    g_pm[gw * Bsz + lane] = m;
    g_ps[gw * Bsz + lane] = s;
    g_pi[gw * Bsz + lane] = bi;
}

// ---------------- merge partials, loss + argmax tokens ----------------------
// 1 block x 256 thr. thread (b = tid&31, c = tid>>5) merges 125 partials.
__global__ void reduce_kernel(int t, const int* __restrict__ target,
                              const float* __restrict__ emb,
                              const float* __restrict__ outb,
                              float* __restrict__ dout) {
    __shared__ float sm[8 * 32], ss[8 * 32];
    __shared__ int   si[8 * 32];
    const int tid = threadIdx.x;
    const int b = tid & 31, c = tid >> 5;

    float m = -INFINITY, s = 0.f; int bi = 0;
    for (int g = c * 125; g < c * 125 + 125; g++) {
        float m2 = g_pm[g * Bsz + b];
        float s2 = g_ps[g * Bsz + b];
        int   i2 = g_pi[g * Bsz + b];
        if (m2 > m) { s = s * __expf(m - m2) + s2; bi = i2; m = m2; }
        else        { s += s2 * __expf(m2 - m); }
    }
    sm[c * 32 + b] = m; ss[c * 32 + b] = s; si[c * 32 + b] = bi;
    __syncthreads();

    if (tid < 32) {
        m = sm[tid]; s = ss[tid]; bi = si[tid];
        #pragma unroll
        for (int c2 = 1; c2 < 8; c2++) {
            float m2 = sm[c2 * 32 + tid];
            float s2 = ss[c2 * 32 + tid];
            int   i2 = si[c2 * 32 + tid];
            if (m2 > m) { s = s * __expf(m - m2) + s2; bi = i2; m = m2; }
            else        { s += s2 * __expf(m2 - m); }
        }
        int gold = target[t * Bsz + tid];
        float acc = 0.f;
        const float* grow = emb + (size_t)gold * Ed;
        #pragma unroll 4
        for (int e0 = 0; e0 < Ed; e0 += 4) {
            float4 w = *(const float4*)(grow + e0);
            acc = fmaf(w.x, g_oe[(e0 + 0) * Bsz + tid], acc);
            acc = fmaf(w.y, g_oe[(e0 + 1) * Bsz + tid], acc);
            acc = fmaf(w.z, g_oe[(e0 + 2) * Bsz + tid], acc);
            acc = fmaf(w.w, g_oe[(e0 + 3) * Bsz + tid], acc);
        }
        float lg = acc + outb[gold];
        float p = expf(lg - m) / s;
        float nll = -logf(p + 1e-20f);
        float maskf = (gold != 0) ? 1.0f : 0.0f;
        float num = nll * maskf;
        float den = maskf;
        #pragma unroll
        for (int o = 16; o > 0; o >>= 1) {
            num += __shfl_down_sync(0xffffffffu, num, o);
            den += __shfl_down_sync(0xffffffffu, den, o);
        }
        dout[t * Bsz + tid] = (float)bi;            // argmax token
        if (tid == 0) atomicAdd(&g_loss, num / fmaxf(den, 1.0f));
    }
}

__global__ void fin_kernel(float* __restrict__ dout, int out_size) {
    if (out_size > TGT_LEN * Bsz) dout[TGT_LEN * Bsz] = g_loss;
}

// ---------------- launch ----------------------------------------------------
extern "C" void kernel_launch(void* const* d_in, const int* in_sizes, int n_in,
                              void* d_out, int out_size) {
    const int*   src  = (const int*)  d_in[0];
    const int*   tgt  = (const int*)  d_in[1];
    const float* emb  = (const float*)d_in[2];
    const float* eWih = (const float*)d_in[3];
    const float* eWhh = (const float*)d_in[4];
    const float* ebih = (const float*)d_in[5];
    const float* ebhh = (const float*)d_in[6];
    const float* dWih = (const float*)d_in[7];
    const float* dWhh = (const float*)d_in[8];
    const float* dbih = (const float*)d_in[9];
    const float* dbhh = (const float*)d_in[10];
    const float* preW = (const float*)d_in[11];
    const float* preb = (const float*)d_in[12];
    const float* outb = (const float*)d_in[13];
    float* out = (float*)d_out;

    init_kernel<<<64, 256>>>();

    // precompute gi for all timesteps (no h dependency)
    gi_kernel<<<SRC_LEN, 256>>>(src, emb, eWih, ebih, 0);
    gi_kernel<<<TGT_LEN, 256>>>(tgt, emb, dWih, dbih, 1);

    // encoder recurrence
    for (int t = 0; t < SRC_LEN; t++)
        hh_kernel<<<128, 256>>>(0, t, eWhh, ebhh, t & 1);
    // after 400 steps, h lives in g_hA

    // decoder recurrence + logits + loss
    for (int t = 0; t < TGT_LEN; t++) {
        int flip = t & 1;
        hh_kernel<<<128, 256>>>(1, t, dWhh, dbhh, flip);
        pre_kernel<<<32, 256>>>(preW, preb, flip);
        logits_kernel<<<125, 256>>>(emb, outb);
        reduce_kernel<<<1, 256>>>(t, tgt, emb, outb, out);
    }

    fin_kernel<<<1, 1>>>(out, out_size);
}

// round 4
// speedup vs baseline: 2.3878x; 2.3878x over previous
#include <cuda_runtime.h>
#include <math.h>

#define SRC_LEN 400
#define TGT_LEN 100
#define Bsz     32
#define Ed      256
#define Hd      512
#define Vd      32000
#define G3H     1536
#define NB      128      // persistent grid size (<= 148 SMs -> co-resident)

// ---------------- device scratch --------------------------------------------
__device__ float  g_gi_enc[(size_t)SRC_LEN * G3H * Bsz];
__device__ float  g_gi_dec[(size_t)TGT_LEN * G3H * Bsz];
__device__ float2 g_h2[2][(Hd / 2) * Bsz];        // h as [k/2][b] float2, dbl-buffered
__device__ float2 g_oe2[(Ed / 2) * Bsz];          // out_emb as [e/2][b] float2
__device__ float  g_pm[NB * Bsz];
__device__ float  g_ps[NB * Bsz];
__device__ int    g_pi[NB * Bsz];
__device__ unsigned g_bar_enc;
__device__ unsigned g_bar_dec;

// ---------------- f32x2 packed FMA ------------------------------------------
__device__ __forceinline__ float2 ffma2(float2 a, float2 b, float2 c) {
    unsigned long long A = *reinterpret_cast<unsigned long long*>(&a);
    unsigned long long B = *reinterpret_cast<unsigned long long*>(&b);
    unsigned long long C = *reinterpret_cast<unsigned long long*>(&c);
    unsigned long long D;
    asm("fma.rn.f32x2 %0, %1, %2, %3;" : "=l"(D) : "l"(A), "l"(B), "l"(C));
    return *reinterpret_cast<float2*>(&D);
}

// ---------------- grid-wide barrier (all NB blocks co-resident) -------------
__device__ __forceinline__ void grid_bar(unsigned* bar, unsigned& target) {
    __threadfence();                 // release this thread's global writes
    __syncthreads();
    if (threadIdx.x == 0) {
        target += NB;
        atomicAdd(bar, 1u);
        while (*((volatile unsigned*)bar) < target) { }
        __threadfence();
    }
    __syncthreads();
}

// ---------------- init -------------------------------------------------------
__global__ void init_kernel() {
    if (threadIdx.x == 0) { g_bar_enc = 0u; g_bar_dec = 0u; }
}

// ---------------- gi precompute (f32x2) --------------------------------------
__global__ void gi_kernel(const int* __restrict__ toks,
                          const float* __restrict__ emb,
                          const float* __restrict__ Wih,
                          const float* __restrict__ bih,
                          int dec_mode) {
    __shared__ float2 xs2[(Ed / 2) * Bsz];   // 32KB, [e2][b]
    __shared__ int    tk[Bsz];
    const int t = blockIdx.x, tid = threadIdx.x;

    if (tid < Bsz) {
        int tok;
        if (dec_mode) tok = (t == 0) ? 1 : toks[(t - 1) * Bsz + tid];
        else          tok = toks[t * Bsz + tid];
        tk[tid] = tok;
    }
    __syncthreads();
    {
        const int b = tid & 31, chunk = tid >> 5;
        const float* erow = emb + (size_t)tk[b] * Ed;
        #pragma unroll
        for (int c = 0; c < 8; c++) {
            int e0 = chunk * 32 + c * 4;
            float4 v = *(const float4*)(erow + e0);
            xs2[(e0 >> 1) * Bsz + b]       = make_float2(v.x, v.y);
            xs2[((e0 >> 1) + 1) * Bsz + b] = make_float2(v.z, v.w);
        }
    }
    __syncthreads();

    const int wid = tid >> 5, lane = tid & 31;
    float* out_t = (dec_mode ? g_gi_dec : g_gi_enc) + (size_t)t * G3H * Bsz;

    for (int jt = 0; jt < 24; jt++) {
        const int j0 = wid * 192 + jt * 8;
        float2 acc[8];
        #pragma unroll
        for (int i = 0; i < 8; i++) acc[i] = make_float2(0.f, 0.f);
        #pragma unroll 2
        for (int e = 0; e < Ed; e += 4) {
            const int e2 = e >> 1;
            float2 x01 = xs2[e2 * Bsz + lane];
            float2 x23 = xs2[(e2 + 1) * Bsz + lane];
            const float* wp = Wih + (size_t)j0 * Ed + e;
            #pragma unroll
            for (int jj = 0; jj < 8; jj++) {
                float4 w = *(const float4*)(wp + (size_t)jj * Ed);
                acc[jj] = ffma2(make_float2(w.x, w.y), x01, acc[jj]);
                acc[jj] = ffma2(make_float2(w.z, w.w), x23, acc[jj]);
            }
        }
        #pragma unroll
        for (int jj = 0; jj < 8; jj++)
            out_t[(size_t)(j0 + jj) * Bsz + lane] = acc[jj].x + acc[jj].y + bih[j0 + jj];
    }
}

// ---------------- shared helpers for persistent kernels ----------------------
// smem float layout offsets
#define WS_F   0                       // 12*512 = 6144 floats
#define HP_F   6144                    // 256*32 float2 = 16384 floats
#define PP_F   (6144 + 16384)          // 1536 floats
#define OES_F  (6144 + 16384 + 1536)   // 128*32 float2 = 8192 floats (dec only)
#define ENC_SMEM_BYTES ((6144 + 16384 + 1536) * 4)
#define DEC_SMEM_BYTES ((6144 + 16384 + 1536 + 8192) * 4)

__device__ __forceinline__ void load_ws(float* ws, const float* __restrict__ Whh, int j0) {
    for (int i = threadIdx.x; i < 12 * 128; i += 256) {
        int r = i >> 7, k4 = i & 127;
        int g = r >> 2, jl = r & 3;
        ((float4*)ws)[r * 128 + k4] =
            *(const float4*)&Whh[((size_t)(g * Hd + j0 + jl)) * Hd + k4 * 4];
    }
}

__device__ __forceinline__ void stage_h(float2* hp, const float2* __restrict__ src) {
    const float4* s = (const float4*)src;
    float4* d = (float4*)hp;
    for (int i = threadIdx.x; i < (Hd * Bsz) / 4; i += 256) d[i] = __ldcg(s + i);
    __syncthreads();
}

// GRU step: block owns j0..j0+3. hp = h_prev smem. writes h_new (cg) to hout.
__device__ __forceinline__ void hh_step(const float* __restrict__ ws,
                                        const float2* __restrict__ hp,
                                        const float* __restrict__ gi_t,
                                        const float* __restrict__ bhh,
                                        float2* __restrict__ hout,
                                        float* __restrict__ pp,
                                        int j0) {
    const int tid = threadIdx.x, wid = tid >> 5, lane = tid & 31;
    const int p = wid >> 2, q = wid & 3;

    float2 acc[6];   // [g*2+jj]
    #pragma unroll
    for (int i = 0; i < 6; i++) acc[i] = make_float2(0.f, 0.f);

    const int kbeg = q * 128;
    #pragma unroll 4
    for (int k = kbeg; k < kbeg + 128; k += 4) {
        const int k2 = k >> 1;
        float2 x01 = hp[k2 * Bsz + lane];
        float2 x23 = hp[(k2 + 1) * Bsz + lane];
        #pragma unroll
        for (int g = 0; g < 3; g++) {
            #pragma unroll
            for (int jj = 0; jj < 2; jj++) {
                float4 w = *(const float4*)&ws[(g * 4 + 2 * p + jj) * Hd + k];
                acc[g * 2 + jj] = ffma2(make_float2(w.x, w.y), x01, acc[g * 2 + jj]);
                acc[g * 2 + jj] = ffma2(make_float2(w.z, w.w), x23, acc[g * 2 + jj]);
            }
        }
    }
    #pragma unroll
    for (int i = 0; i < 6; i++)
        pp[((q * 2 + p) * 6 + i) * Bsz + lane] = acc[i].x + acc[i].y;
    __syncthreads();

    if (wid < 2) {
        const int fp = wid;
        float s[6];
        #pragma unroll
        for (int i = 0; i < 6; i++) {
            float v = 0.f;
            #pragma unroll
            for (int q2 = 0; q2 < 4; q2++) v += pp[((q2 * 2 + fp) * 6 + i) * Bsz + lane];
            s[i] = v;
        }
        float2 hold = hp[(j0 / 2 + fp) * Bsz + lane];
        float hn[2];
        #pragma unroll
        for (int jj = 0; jj < 2; jj++) {
            int j = j0 + 2 * fp + jj;
            float ghr = s[0 + jj] + bhh[j];
            float ghz = s[2 + jj] + bhh[Hd + j];
            float ghn = s[4 + jj] + bhh[2 * Hd + j];
            float gir = gi_t[(size_t)(0 * Hd + j) * Bsz + lane];
            float giz = gi_t[(size_t)(1 * Hd + j) * Bsz + lane];
            float gin = gi_t[(size_t)(2 * Hd + j) * Bsz + lane];
            float r = 1.0f / (1.0f + expf(-(gir + ghr)));
            float z = 1.0f / (1.0f + expf(-(giz + ghz)));
            float n = tanhf(gin + r * ghn);
            float ho = jj ? hold.y : hold.x;
            hn[jj] = (1.0f - z) * n + z * ho;
        }
        __stcg(&hout[(j0 / 2 + fp) * Bsz + lane], make_float2(hn[0], hn[1]));
    }
}

// ---------------- persistent encoder -----------------------------------------
__global__ void __launch_bounds__(256, 1)
enc_persist(const float* __restrict__ Whh, const float* __restrict__ bhh) {
    extern __shared__ float sm[];
    float*  ws = sm + WS_F;
    float2* hp = (float2*)(sm + HP_F);
    float*  pp = sm + PP_F;
    const int j0 = blockIdx.x * 4;

    load_ws(ws, Whh, j0);
    for (int i = threadIdx.x; i < Hd * Bsz; i += 256) ((float*)hp)[i] = 0.f;
    __syncthreads();

    unsigned tgt = 0;
    for (int t = 0; t < SRC_LEN; t++) {
        hh_step(ws, hp, g_gi_enc + (size_t)t * G3H * Bsz, bhh, g_h2[t & 1], pp, j0);
        grid_bar(&g_bar_enc, tgt);
        stage_h(hp, g_h2[t & 1]);
    }
    // final h in g_h2[(SRC_LEN-1)&1] = g_h2[1]
}

// ---------------- decoder phase helpers --------------------------------------
__device__ __forceinline__ void pre_step(const float2* __restrict__ hp,
                                         const float* __restrict__ preW,
                                         const float* __restrict__ preb,
                                         float* __restrict__ pp, int bid) {
    const int tid = threadIdx.x, wid = tid >> 5, lane = tid & 31;
    const int e0 = bid * 2;
    float2 a0 = make_float2(0.f, 0.f), a1 = a0;
    const int kb = wid * 64;
    #pragma unroll 4
    for (int k = kb; k < kb + 64; k += 4) {
        const int k2 = k >> 1;
        float2 x01 = hp[k2 * Bsz + lane];
        float2 x23 = hp[(k2 + 1) * Bsz + lane];
        float4 w0 = *(const float4*)&preW[(size_t)e0 * Hd + k];
        float4 w1 = *(const float4*)&preW[(size_t)(e0 + 1) * Hd + k];
        a0 = ffma2(make_float2(w0.x, w0.y), x01, a0);
        a0 = ffma2(make_float2(w0.z, w0.w), x23, a0);
        a1 = ffma2(make_float2(w1.x, w1.y), x01, a1);
        a1 = ffma2(make_float2(w1.z, w1.w), x23, a1);
    }
    pp[(wid * 2 + 0) * Bsz + lane] = a0.x + a0.y;
    pp[(wid * 2 + 1) * Bsz + lane] = a1.x + a1.y;
    __syncthreads();
    if (wid == 0) {
        float s0 = 0.f, s1 = 0.f;
        #pragma unroll
        for (int w = 0; w < 8; w++) {
            s0 += pp[(w * 2 + 0) * Bsz + lane];
            s1 += pp[(w * 2 + 1) * Bsz + lane];
        }
        __stcg(&g_oe2[bid * Bsz + lane], make_float2(s0 + preb[e0], s1 + preb[e0 + 1]));
    }
}

__device__ __forceinline__ void logits_step(const float2* __restrict__ oes,
                                            const float* __restrict__ emb,
                                            const float* __restrict__ outb,
                                            float* __restrict__ pp, int bid) {
    const int tid = threadIdx.x, wid = tid >> 5, lane = tid & 31;
    const int v0 = bid * 250, vend = v0 + 250;

    float m = -INFINITY, s = 0.f;
    int bi = 0;

    const int base = v0 + wid * 32;
    for (int vt = 0; vt < 4; vt++) {
        const int vb = base + vt * 8;
        if (vb >= vend) break;
        int nv = vend - vb; if (nv > 8) nv = 8;

        const float* rowp[8];
        #pragma unroll
        for (int vv = 0; vv < 8; vv++) {
            int v = (vv < nv) ? (vb + vv) : vb;
            rowp[vv] = emb + (size_t)v * Ed;
        }
        float2 acc[8];
        #pragma unroll
        for (int i = 0; i < 8; i++) acc[i] = make_float2(0.f, 0.f);

        #pragma unroll 2
        for (int e = 0; e < Ed; e += 4) {
            const int e2 = e >> 1;
            float2 x01 = oes[e2 * Bsz + lane];
            float2 x23 = oes[(e2 + 1) * Bsz + lane];
            #pragma unroll
            for (int vv = 0; vv < 8; vv++) {
                float4 w = *(const float4*)(rowp[vv] + e);
                acc[vv] = ffma2(make_float2(w.x, w.y), x01, acc[vv]);
                acc[vv] = ffma2(make_float2(w.z, w.w), x23, acc[vv]);
            }
        }
        #pragma unroll
        for (int vv = 0; vv < 8; vv++) {
            if (vv < nv) {
                float l = acc[vv].x + acc[vv].y + __ldg(&outb[vb + vv]);
                if (l > m) { s = s * __expf(m - l) + 1.0f; m = l; bi = vb + vv; }
                else       { s += __expf(l - m); }
            }
        }
    }
    // block merge (ascending warp order)
    pp[wid * Bsz + lane] = m;
    pp[256 + wid * Bsz + lane] = s;
    ((int*)pp)[512 + wid * Bsz + lane] = bi;
    __syncthreads();
    if (wid == 0) {
        float M = pp[lane], S = pp[256 + lane];
        int   I = ((int*)pp)[512 + lane];
        #pragma unroll
        for (int w = 1; w < 8; w++) {
            float m2 = pp[w * Bsz + lane];
            float s2 = pp[256 + w * Bsz + lane];
            int   i2 = ((int*)pp)[512 + w * Bsz + lane];
            if (m2 > M) { S = S * __expf(M - m2) + s2; I = i2; M = m2; }
            else        { S += s2 * __expf(m2 - M); }
        }
        __stcg(&g_pm[bid * Bsz + lane], M);
        __stcg(&g_ps[bid * Bsz + lane], S);
        __stcg(&g_pi[bid * Bsz + lane], I);
    }
}

__device__ __forceinline__ void reduce_step(int t, const int* __restrict__ tgt,
                                            const float* __restrict__ emb,
                                            const float* __restrict__ outb,
                                            const float2* __restrict__ oes,
                                            float* __restrict__ pp,
                                            float* __restrict__ dout,
                                            float& lsum) {
    const int tid = threadIdx.x, b = tid & 31, c = tid >> 5;
    float m = -INFINITY, s = 0.f;
    int bi = 0;
    for (int g = c * 16; g < c * 16 + 16; g++) {           // ascending v order
        float m2 = __ldcg(&g_pm[g * Bsz + b]);
        float s2 = __ldcg(&g_ps[g * Bsz + b]);
        int   i2 = __ldcg(&g_pi[g * Bsz + b]);
        if (m2 > m) { s = s * __expf(m - m2) + s2; bi = i2; m = m2; }
        else        { s += s2 * __expf(m2 - m); }
    }
    pp[c * Bsz + b] = m;
    pp[256 + c * Bsz + b] = s;
    ((int*)pp)[512 + c * Bsz + b] = bi;
    __syncthreads();
    if (tid < 32) {
        m = pp[tid]; s = pp[256 + tid]; bi = ((int*)pp)[512 + tid];
        #pragma unroll
        for (int c2 = 1; c2 < 8; c2++) {
            float m2 = pp[c2 * Bsz + tid];
            float s2 = pp[256 + c2 * Bsz + tid];
            int   i2 = ((int*)pp)[512 + c2 * Bsz + tid];
            if (m2 > m) { s = s * __expf(m - m2) + s2; bi = i2; m = m2; }
            else        { s += s2 * __expf(m2 - m); }
        }
        int gold = tgt[t * Bsz + tid];
        float2 acc = make_float2(0.f, 0.f);
        const float* grow = emb + (size_t)gold * Ed;
        #pragma unroll 4
        for (int e = 0; e < Ed; e += 4) {
            float4 w = *(const float4*)(grow + e);
            acc = ffma2(make_float2(w.x, w.y), oes[(e >> 1) * Bsz + tid], acc);
            acc = ffma2(make_float2(w.z, w.w), oes[((e >> 1) + 1) * Bsz + tid], acc);
        }
        float lg = acc.x + acc.y + outb[gold];
        float prob = expf(lg - m) / s;
        float nll = -logf(prob + 1e-20f);
        float maskf = (gold != 0) ? 1.0f : 0.0f;
        float num = nll * maskf, den = maskf;
        #pragma unroll
        for (int o = 16; o > 0; o >>= 1) {
            num += __shfl_down_sync(0xffffffffu, num, o);
            den += __shfl_down_sync(0xffffffffu, den, o);
        }
        dout[t * Bsz + tid] = (float)bi;
        if (tid == 0) lsum += num / fmaxf(den, 1.0f);
    }
    __syncthreads();
}

// ---------------- persistent decoder -----------------------------------------
__global__ void __launch_bounds__(256, 1)
dec_persist(const float* __restrict__ Whh, const float* __restrict__ bhh,
            const float* __restrict__ preW, const float* __restrict__ preb,
            const float* __restrict__ emb,  const float* __restrict__ outb,
            const int* __restrict__ tgt, float* __restrict__ dout, int out_size) {
    extern __shared__ float sm[];
    float*  ws  = sm + WS_F;
    float2* hp  = (float2*)(sm + HP_F);
    float*  pp  = sm + PP_F;
    float2* oes = (float2*)(sm + OES_F);
    const int bid = blockIdx.x;
    const int j0 = bid * 4;

    load_ws(ws, Whh, j0);
    __syncthreads();
    stage_h(hp, g_h2[1]);                 // encoder final hidden

    float lsum = 0.f;
    unsigned tc = 0;
    for (int t = 0; t < TGT_LEN; t++) {
        hh_step(ws, hp, g_gi_dec + (size_t)t * G3H * Bsz, bhh, g_h2[t & 1], pp, j0);
        grid_bar(&g_bar_dec, tc);
        stage_h(hp, g_h2[t & 1]);         // hp = h_new

        pre_step(hp, preW, preb, pp, bid);
        grid_bar(&g_bar_dec, tc);
        {   // stage oe: Ed*Bsz floats = (Ed*Bsz)/4 float4s  (R3 bug: was /8)
            const float4* s4 = (const float4*)g_oe2;
            float4* d4 = (float4*)oes;
            for (int i = threadIdx.x; i < (Ed * Bsz) / 4; i += 256) d4[i] = __ldcg(s4 + i);
            __syncthreads();
        }

        logits_step(oes, emb, outb, pp, bid);
        grid_bar(&g_bar_dec, tc);

        if (bid == 0)
            reduce_step(t, tgt, emb, outb, oes, pp, dout, lsum);
    }
    if (bid == 0 && threadIdx.x == 0 && out_size > TGT_LEN * Bsz)
        dout[TGT_LEN * Bsz] = lsum;
}

// ---------------- launch ------------------------------------------------------
extern "C" void kernel_launch(void* const* d_in, const int* in_sizes, int n_in,
                              void* d_out, int out_size) {
    const int*   src  = (const int*)  d_in[0];
    const int*   tgt  = (const int*)  d_in[1];
    const float* emb  = (const float*)d_in[2];
    const float* eWih = (const float*)d_in[3];
    const float* eWhh = (const float*)d_in[4];
    const float* ebih = (const float*)d_in[5];
    const float* ebhh = (const float*)d_in[6];
    const float* dWih = (const float*)d_in[7];
    const float* dWhh = (const float*)d_in[8];
    const float* dbih = (const float*)d_in[9];
    const float* dbhh = (const float*)d_in[10];
    const float* preW = (const float*)d_in[11];
    const float* preb = (const float*)d_in[12];
    const float* outb = (const float*)d_in[13];
    float* out = (float*)d_out;

    static int attr_done = 0;
    if (!attr_done) {
        cudaFuncSetAttribute(enc_persist, cudaFuncAttributeMaxDynamicSharedMemorySize,
                             ENC_SMEM_BYTES);
        cudaFuncSetAttribute(dec_persist, cudaFuncAttributeMaxDynamicSharedMemorySize,
                             DEC_SMEM_BYTES);
        attr_done = 1;
    }

    init_kernel<<<1, 32>>>();
    gi_kernel<<<SRC_LEN, 256>>>(src, emb, eWih, ebih, 0);
    gi_kernel<<<TGT_LEN, 256>>>(tgt, emb, dWih, dbih, 1);
    enc_persist<<<NB, 256, ENC_SMEM_BYTES>>>(eWhh, ebhh);
    dec_persist<<<NB, 256, DEC_SMEM_BYTES>>>(dWhh, dbhh, preW, preb, emb, outb,
                                             tgt, out, out_size);
}

// round 5
// speedup vs baseline: 4.1927x; 1.7559x over previous
#include <cuda_runtime.h>
#include <math.h>

#define SRC_LEN 400
#define TGT_LEN 100
#define Bsz     32
#define Ed      256
#define Hd      512
#define Vd      32000
#define G3H     1536
#define NB      128      // persistent grid size (<= 148 SMs -> co-resident)
#define NCH     125      // logits v-chunks of 256
#define TPAIRS  50       // 100 timesteps / 2 per block

// ---------------- device scratch --------------------------------------------
__device__ float  g_gi_enc[(size_t)SRC_LEN * G3H * Bsz];
__device__ float  g_gi_dec[(size_t)TGT_LEN * G3H * Bsz];
__device__ float2 g_h2[2][(Hd / 2) * Bsz];                 // encoder h exchange
__device__ float2 g_hall[(size_t)TGT_LEN * (Hd / 2) * Bsz]; // all decoder h_t
__device__ float2 g_oeall[(size_t)TGT_LEN * (Ed / 2) * Bsz];
__device__ float  g_pm[(size_t)TGT_LEN * NCH * Bsz];
__device__ float  g_ps[(size_t)TGT_LEN * NCH * Bsz];
__device__ int    g_pi[(size_t)TGT_LEN * NCH * Bsz];
__device__ float  g_loss_t[TGT_LEN];
__device__ unsigned g_bar_enc;
__device__ unsigned g_bar_dec;

// ---------------- f32x2 packed FMA ------------------------------------------
__device__ __forceinline__ float2 ffma2(float2 a, float2 b, float2 c) {
    unsigned long long A = *reinterpret_cast<unsigned long long*>(&a);
    unsigned long long B = *reinterpret_cast<unsigned long long*>(&b);
    unsigned long long C = *reinterpret_cast<unsigned long long*>(&c);
    unsigned long long D;
    asm("fma.rn.f32x2 %0, %1, %2, %3;" : "=l"(D) : "l"(A), "l"(B), "l"(C));
    return *reinterpret_cast<float2*>(&D);
}

// ---------------- grid-wide barrier -----------------------------------------
__device__ __forceinline__ void grid_bar(unsigned* bar, unsigned& target) {
    __threadfence();
    __syncthreads();
    if (threadIdx.x == 0) {
        target += NB;
        atomicAdd(bar, 1u);
        while (*((volatile unsigned*)bar) < target) { }
        __threadfence();
    }
    __syncthreads();
}

__global__ void init_kernel() {
    if (threadIdx.x == 0) { g_bar_enc = 0u; g_bar_dec = 0u; }
}

// ---------------- gi precompute ----------------------------------------------
__global__ void gi_kernel(const int* __restrict__ toks,
                          const float* __restrict__ emb,
                          const float* __restrict__ Wih,
                          const float* __restrict__ bih,
                          int dec_mode) {
    __shared__ float2 xs2[(Ed / 2) * Bsz];
    __shared__ int    tk[Bsz];
    const int t = blockIdx.x, tid = threadIdx.x;

    if (tid < Bsz) {
        int tok;
        if (dec_mode) tok = (t == 0) ? 1 : toks[(t - 1) * Bsz + tid];
        else          tok = toks[t * Bsz + tid];
        tk[tid] = tok;
    }
    __syncthreads();
    {
        const int b = tid & 31, chunk = tid >> 5;
        const float* erow = emb + (size_t)tk[b] * Ed;
        #pragma unroll
        for (int c = 0; c < 8; c++) {
            int e0 = chunk * 32 + c * 4;
            float4 v = *(const float4*)(erow + e0);
            xs2[(e0 >> 1) * Bsz + b]       = make_float2(v.x, v.y);
            xs2[((e0 >> 1) + 1) * Bsz + b] = make_float2(v.z, v.w);
        }
    }
    __syncthreads();

    const int wid = tid >> 5, lane = tid & 31;
    float* out_t = (dec_mode ? g_gi_dec : g_gi_enc) + (size_t)t * G3H * Bsz;

    for (int jt = 0; jt < 24; jt++) {
        const int j0 = wid * 192 + jt * 8;
        float2 acc[8];
        #pragma unroll
        for (int i = 0; i < 8; i++) acc[i] = make_float2(0.f, 0.f);
        #pragma unroll 2
        for (int e = 0; e < Ed; e += 4) {
            const int e2 = e >> 1;
            float2 x01 = xs2[e2 * Bsz + lane];
            float2 x23 = xs2[(e2 + 1) * Bsz + lane];
            const float* wp = Wih + (size_t)j0 * Ed + e;
            #pragma unroll
            for (int jj = 0; jj < 8; jj++) {
                float4 w = *(const float4*)(wp + (size_t)jj * Ed);
                acc[jj] = ffma2(make_float2(w.x, w.y), x01, acc[jj]);
                acc[jj] = ffma2(make_float2(w.z, w.w), x23, acc[jj]);
            }
        }
        #pragma unroll
        for (int jj = 0; jj < 8; jj++)
            out_t[(size_t)(j0 + jj) * Bsz + lane] = acc[jj].x + acc[jj].y + bih[j0 + jj];
    }
}

// ---------------- persistent GRU helpers -------------------------------------
#define WS_F   0
#define HP_F   6144
#define PP_F   (6144 + 16384)
#define REC_SMEM_BYTES ((6144 + 16384 + 1536) * 4)

__device__ __forceinline__ void load_ws(float* ws, const float* __restrict__ Whh, int j0) {
    for (int i = threadIdx.x; i < 12 * 128; i += 256) {
        int r = i >> 7, k4 = i & 127;
        int g = r >> 2, jl = r & 3;
        ((float4*)ws)[r * 128 + k4] =
            *(const float4*)&Whh[((size_t)(g * Hd + j0 + jl)) * Hd + k4 * 4];
    }
}

__device__ __forceinline__ void stage_h(float2* hp, const float2* __restrict__ src) {
    const float4* s = (const float4*)src;
    float4* d = (float4*)hp;
    for (int i = threadIdx.x; i < (Hd * Bsz) / 4; i += 256) d[i] = __ldcg(s + i);
    __syncthreads();
}

__device__ __forceinline__ void hh_step(const float* __restrict__ ws,
                                        const float2* __restrict__ hp,
                                        const float* __restrict__ gi_t,
                                        const float* __restrict__ bhh,
                                        float2* __restrict__ hout,
                                        float* __restrict__ pp,
                                        int j0) {
    const int tid = threadIdx.x, wid = tid >> 5, lane = tid & 31;
    const int p = wid >> 2, q = wid & 3;

    // prefetch gate inputs (cold DRAM) before the k-loop hides their latency
    float pg[6];
    float2 hold = make_float2(0.f, 0.f);
    if (wid < 2) {
        const int j = j0 + 2 * wid;
        pg[0] = __ldcg(&gi_t[(size_t)(0 * Hd + j) * Bsz + lane]);
        pg[1] = __ldcg(&gi_t[(size_t)(0 * Hd + j + 1) * Bsz + lane]);
        pg[2] = __ldcg(&gi_t[(size_t)(1 * Hd + j) * Bsz + lane]);
        pg[3] = __ldcg(&gi_t[(size_t)(1 * Hd + j + 1) * Bsz + lane]);
        pg[4] = __ldcg(&gi_t[(size_t)(2 * Hd + j) * Bsz + lane]);
        pg[5] = __ldcg(&gi_t[(size_t)(2 * Hd + j + 1) * Bsz + lane]);
        hold  = hp[(j0 / 2 + wid) * Bsz + lane];
    }

    float2 acc[6];
    #pragma unroll
    for (int i = 0; i < 6; i++) acc[i] = make_float2(0.f, 0.f);

    const int kbeg = q * 128;
    #pragma unroll 4
    for (int k = kbeg; k < kbeg + 128; k += 4) {
        const int k2 = k >> 1;
        float2 x01 = hp[k2 * Bsz + lane];
        float2 x23 = hp[(k2 + 1) * Bsz + lane];
        #pragma unroll
        for (int g = 0; g < 3; g++) {
            #pragma unroll
            for (int jj = 0; jj < 2; jj++) {
                float4 w = *(const float4*)&ws[(g * 4 + 2 * p + jj) * Hd + k];
                acc[g * 2 + jj] = ffma2(make_float2(w.x, w.y), x01, acc[g * 2 + jj]);
                acc[g * 2 + jj] = ffma2(make_float2(w.z, w.w), x23, acc[g * 2 + jj]);
            }
        }
    }
    #pragma unroll
    for (int i = 0; i < 6; i++)
        pp[((q * 2 + p) * 6 + i) * Bsz + lane] = acc[i].x + acc[i].y;
    __syncthreads();

    if (wid < 2) {
        const int fp = wid;
        float s[6];
        #pragma unroll
        for (int i = 0; i < 6; i++) {
            float v = 0.f;
            #pragma unroll
            for (int q2 = 0; q2 < 4; q2++) v += pp[((q2 * 2 + fp) * 6 + i) * Bsz + lane];
            s[i] = v;
        }
        float hn[2];
        #pragma unroll
        for (int jj = 0; jj < 2; jj++) {
            int j = j0 + 2 * fp + jj;
            float ghr = s[0 + jj] + bhh[j];
            float ghz = s[2 + jj] + bhh[Hd + j];
            float ghn = s[4 + jj] + bhh[2 * Hd + j];
            float r = 1.0f / (1.0f + expf(-(pg[0 + jj] + ghr)));
            float z = 1.0f / (1.0f + expf(-(pg[2 + jj] + ghz)));
            float n = tanhf(pg[4 + jj] + r * ghn);
            float ho = jj ? hold.y : hold.x;
            hn[jj] = (1.0f - z) * n + z * ho;
        }
        __stcg(&hout[(j0 / 2 + fp) * Bsz + lane], make_float2(hn[0], hn[1]));
    }
}

// ---------------- persistent encoder -----------------------------------------
__global__ void __launch_bounds__(256, 1)
enc_persist(const float* __restrict__ Whh, const float* __restrict__ bhh) {
    extern __shared__ float sm[];
    float*  ws = sm + WS_F;
    float2* hp = (float2*)(sm + HP_F);
    float*  pp = sm + PP_F;
    const int j0 = blockIdx.x * 4;

    load_ws(ws, Whh, j0);
    for (int i = threadIdx.x; i < Hd * Bsz; i += 256) ((float*)hp)[i] = 0.f;
    __syncthreads();

    unsigned tgt = 0;
    for (int t = 0; t < SRC_LEN; t++) {
        hh_step(ws, hp, g_gi_enc + (size_t)t * G3H * Bsz, bhh, g_h2[t & 1], pp, j0);
        grid_bar(&g_bar_enc, tgt);
        stage_h(hp, g_h2[t & 1]);
    }
    // final h in g_h2[1]
}

// ---------------- decoder phase A: recurrence only ----------------------------
__global__ void __launch_bounds__(256, 1)
dec_rec(const float* __restrict__ Whh, const float* __restrict__ bhh) {
    extern __shared__ float sm[];
    float*  ws = sm + WS_F;
    float2* hp = (float2*)(sm + HP_F);
    float*  pp = sm + PP_F;
    const int j0 = blockIdx.x * 4;

    load_ws(ws, Whh, j0);
    __syncthreads();
    stage_h(hp, g_h2[1]);

    unsigned tc = 0;
    for (int t = 0; t < TGT_LEN; t++) {
        float2* hall_t = &g_hall[(size_t)t * (Hd / 2) * Bsz];
        hh_step(ws, hp, g_gi_dec + (size_t)t * G3H * Bsz, bhh, hall_t, pp, j0);
        grid_bar(&g_bar_dec, tc);
        stage_h(hp, hall_t);
    }
}

// ---------------- decoder phase B: batched pre (oe_all) -----------------------
__global__ void __launch_bounds__(256)
pre_all(const float* __restrict__ preW, const float* __restrict__ preb) {
    extern __shared__ float sm[];
    float2* hs = (float2*)sm;     // 64KB
    const int t = blockIdx.x, tid = threadIdx.x;
    {
        const float4* s4 = (const float4*)&g_hall[(size_t)t * (Hd / 2) * Bsz];
        float4* d4 = (float4*)hs;
        for (int i = tid; i < (Hd * Bsz) / 4; i += 256) d4[i] = __ldg(s4 + i);
        __syncthreads();
    }
    const int wid = tid >> 5, lane = tid & 31;
    for (int grp = 0; grp < 4; grp++) {
        const int e0 = wid * 32 + grp * 8;
        float2 acc[8];
        #pragma unroll
        for (int i = 0; i < 8; i++) acc[i] = make_float2(0.f, 0.f);
        const float* wp = preW + (size_t)e0 * Hd;
        #pragma unroll 2
        for (int k = 0; k < Hd; k += 4) {
            const int k2 = k >> 1;
            float2 x01 = hs[k2 * Bsz + lane];
            float2 x23 = hs[(k2 + 1) * Bsz + lane];
            #pragma unroll
            for (int r = 0; r < 8; r++) {
                float4 w = *(const float4*)(wp + (size_t)r * Hd + k);
                acc[r] = ffma2(make_float2(w.x, w.y), x01, acc[r]);
                acc[r] = ffma2(make_float2(w.z, w.w), x23, acc[r]);
            }
        }
        #pragma unroll
        for (int i = 0; i < 4; i++) {
            float v0 = acc[2 * i].x     + acc[2 * i].y     + preb[e0 + 2 * i];
            float v1 = acc[2 * i + 1].x + acc[2 * i + 1].y + preb[e0 + 2 * i + 1];
            g_oeall[((size_t)t * (Ed / 2) + (e0 >> 1) + i) * Bsz + lane] =
                make_float2(v0, v1);
        }
    }
}

// ---------------- decoder phase C: batched logits + online softmax ------------
// block = (chunk c of 256 v) x (timestep pair t0, t0+1). 8 warps x 32 v each.
__global__ void __launch_bounds__(256)
logits_all(const float* __restrict__ emb, const float* __restrict__ outb) {
    extern __shared__ float sm[];
    float2* oesA = (float2*)sm;
    float2* oesB = ((float2*)sm) + (Ed / 2) * Bsz;
    float*  mm = sm + 16384;            // [2][8][32]
    float*  ms = mm + 512;
    int*    mi = (int*)(ms + 512);

    const int bid = blockIdx.x;
    const int c = bid / TPAIRS, p = bid % TPAIRS;
    const int t0 = 2 * p;
    const int tid = threadIdx.x, wid = tid >> 5, lane = tid & 31;

    {
        const float4* sA = (const float4*)&g_oeall[(size_t)t0 * (Ed / 2) * Bsz];
        const float4* sB = (const float4*)&g_oeall[(size_t)(t0 + 1) * (Ed / 2) * Bsz];
        float4* dA = (float4*)oesA;
        float4* dB = (float4*)oesB;
        for (int i = tid; i < (Ed * Bsz) / 4; i += 256) {
            dA[i] = __ldg(sA + i);
            dB[i] = __ldg(sB + i);
        }
        __syncthreads();
    }

    const int base = c * 256 + wid * 32;
    float m0 = -INFINITY, s0 = 0.f; int b0 = 0;
    float m1 = -INFINITY, s1 = 0.f; int b1 = 0;

    for (int vt = 0; vt < 4; vt++) {
        const int vb = base + vt * 8;
        float2 accA[8], accB[8];
        #pragma unroll
        for (int i = 0; i < 8; i++) { accA[i] = make_float2(0.f, 0.f); accB[i] = accA[i]; }
        const float* ep = emb + (size_t)vb * Ed;

        #pragma unroll 2
        for (int e = 0; e < Ed; e += 4) {
            const int e2 = e >> 1;
            float2 xa01 = oesA[e2 * Bsz + lane];
            float2 xa23 = oesA[(e2 + 1) * Bsz + lane];
            float2 xb01 = oesB[e2 * Bsz + lane];
            float2 xb23 = oesB[(e2 + 1) * Bsz + lane];
            #pragma unroll
            for (int vv = 0; vv < 8; vv++) {
                float4 w = *(const float4*)(ep + (size_t)vv * Ed + e);
                float2 w01 = make_float2(w.x, w.y), w23 = make_float2(w.z, w.w);
                accA[vv] = ffma2(w01, xa01, accA[vv]);
                accA[vv] = ffma2(w23, xa23, accA[vv]);
                accB[vv] = ffma2(w01, xb01, accB[vv]);
                accB[vv] = ffma2(w23, xb23, accB[vv]);
            }
        }
        #pragma unroll
        for (int vv = 0; vv < 8; vv++) {
            float lb = outb[vb + vv];
            float l0 = accA[vv].x + accA[vv].y + lb;
            if (l0 > m0) { s0 = s0 * __expf(m0 - l0) + 1.0f; m0 = l0; b0 = vb + vv; }
            else         { s0 += __expf(l0 - m0); }
            float l1 = accB[vv].x + accB[vv].y + lb;
            if (l1 > m1) { s1 = s1 * __expf(m1 - l1) + 1.0f; m1 = l1; b1 = vb + vv; }
            else         { s1 += __expf(l1 - m1); }
        }
    }
    mm[(0 * 8 + wid) * 32 + lane] = m0; ms[(0 * 8 + wid) * 32 + lane] = s0;
    mi[(0 * 8 + wid) * 32 + lane] = b0;
    mm[(1 * 8 + wid) * 32 + lane] = m1; ms[(1 * 8 + wid) * 32 + lane] = s1;
    mi[(1 * 8 + wid) * 32 + lane] = b1;
    __syncthreads();

    if (wid < 2) {
        const int tt = wid;
        float M = mm[(tt * 8 + 0) * 32 + lane];
        float S = ms[(tt * 8 + 0) * 32 + lane];
        int   I = mi[(tt * 8 + 0) * 32 + lane];
        #pragma unroll
        for (int w = 1; w < 8; w++) {
            float m2 = mm[(tt * 8 + w) * 32 + lane];
            float s2 = ms[(tt * 8 + w) * 32 + lane];
            int   i2 = mi[(tt * 8 + w) * 32 + lane];
            if (m2 > M) { S = S * __expf(M - m2) + s2; I = i2; M = m2; }
            else        { S += s2 * __expf(m2 - M); }
        }
        const size_t idx = ((size_t)(t0 + tt) * NCH + c) * 32 + lane;
        g_pm[idx] = M; g_ps[idx] = S; g_pi[idx] = I;
    }
}

// ---------------- decoder phase D: per-t merge, tokens, loss ------------------
__global__ void __launch_bounds__(256)
merge_all(const int* __restrict__ tgt, const float* __restrict__ emb,
          const float* __restrict__ outb, float* __restrict__ dout) {
    __shared__ float smm[8 * 32], sms[8 * 32];
    __shared__ int   smi[8 * 32];
    const int t = blockIdx.x, tid = threadIdx.x, b = tid & 31, cg = tid >> 5;

    float m = -INFINITY, s = 0.f; int bi = 0;
    const int cb = cg * 16, ce = (cb + 16 < NCH) ? cb + 16 : NCH;
    for (int c = cb; c < ce; c++) {
        const size_t idx = ((size_t)t * NCH + c) * 32 + b;
        float m2 = g_pm[idx], s2 = g_ps[idx];
        int   i2 = g_pi[idx];
        if (m2 > m) { s = s * __expf(m - m2) + s2; bi = i2; m = m2; }
        else        { s += s2 * __expf(m2 - m); }
    }
    smm[cg * 32 + b] = m; sms[cg * 32 + b] = s; smi[cg * 32 + b] = bi;
    __syncthreads();

    if (tid < 32) {
        m = smm[tid]; s = sms[tid]; bi = smi[tid];
        #pragma unroll
        for (int c2 = 1; c2 < 8; c2++) {
            float m2 = smm[c2 * 32 + tid];
            float s2 = sms[c2 * 32 + tid];
            int   i2 = smi[c2 * 32 + tid];
            if (m2 > m) { s = s * __expf(m - m2) + s2; bi = i2; m = m2; }
            else        { s += s2 * __expf(m2 - m); }
        }
        int gold = tgt[t * Bsz + tid];
        float2 acc = make_float2(0.f, 0.f);
        const float* grow = emb + (size_t)gold * Ed;
        #pragma unroll 4
        for (int e = 0; e < Ed; e += 4) {
            float4 w = *(const float4*)(grow + e);
            float2 o01 = g_oeall[((size_t)t * (Ed / 2) + (e >> 1)) * Bsz + tid];
            float2 o23 = g_oeall[((size_t)t * (Ed / 2) + (e >> 1) + 1) * Bsz + tid];
            acc = ffma2(make_float2(w.x, w.y), o01, acc);
            acc = ffma2(make_float2(w.z, w.w), o23, acc);
        }
        float lg = acc.x + acc.y + outb[gold];
        float prob = expf(lg - m) / s;
        float nll = -logf(prob + 1e-20f);
        float maskf = (gold != 0) ? 1.0f : 0.0f;
        float num = nll * maskf, den = maskf;
        #pragma unroll
        for (int o = 16; o > 0; o >>= 1) {
            num += __shfl_down_sync(0xffffffffu, num, o);
            den += __shfl_down_sync(0xffffffffu, den, o);
        }
        dout[t * Bsz + tid] = (float)bi;
        if (tid == 0) g_loss_t[t] = num / fmaxf(den, 1.0f);
    }
}

__global__ void loss_fin(float* __restrict__ dout, int out_size) {
    if (out_size <= TGT_LEN * Bsz) return;
    const int lane = threadIdx.x;
    float s = 0.f;
    for (int t = lane; t < TGT_LEN; t += 32) s += g_loss_t[t];
    #pragma unroll
    for (int o = 16; o > 0; o >>= 1) s += __shfl_down_sync(0xffffffffu, s, o);
    if (lane == 0) dout[TGT_LEN * Bsz] = s;
}

// ---------------- launch ------------------------------------------------------
extern "C" void kernel_launch(void* const* d_in, const int* in_sizes, int n_in,
                              void* d_out, int out_size) {
    const int*   src  = (const int*)  d_in[0];
    const int*   tgt  = (const int*)  d_in[1];
    const float* emb  = (const float*)d_in[2];
    const float* eWih = (const float*)d_in[3];
    const float* eWhh = (const float*)d_in[4];
    const float* ebih = (const float*)d_in[5];
    const float* ebhh = (const float*)d_in[6];
    const float* dWih = (const float*)d_in[7];
    const float* dWhh = (const float*)d_in[8];
    const float* dbih = (const float*)d_in[9];
    const float* dbhh = (const float*)d_in[10];
    const float* preW = (const float*)d_in[11];
    const float* preb = (const float*)d_in[12];
    const float* outb = (const float*)d_in[13];
    float* out = (float*)d_out;

    static int attr_done = 0;
    if (!attr_done) {
        cudaFuncSetAttribute(enc_persist, cudaFuncAttributeMaxDynamicSharedMemorySize,
                             REC_SMEM_BYTES);
        cudaFuncSetAttribute(dec_rec, cudaFuncAttributeMaxDynamicSharedMemorySize,
                             REC_SMEM_BYTES);
        cudaFuncSetAttribute(pre_all, cudaFuncAttributeMaxDynamicSharedMemorySize,
                             65536);
        cudaFuncSetAttribute(logits_all, cudaFuncAttributeMaxDynamicSharedMemorySize,
                             (16384 + 1536) * 4);
        attr_done = 1;
    }

    init_kernel<<<1, 32>>>();
    gi_kernel<<<SRC_LEN, 256>>>(src, emb, eWih, ebih, 0);
    gi_kernel<<<TGT_LEN, 256>>>(tgt, emb, dWih, dbih, 1);
    enc_persist<<<NB, 256, REC_SMEM_BYTES>>>(eWhh, ebhh);
    dec_rec<<<NB, 256, REC_SMEM_BYTES>>>(dWhh, dbhh);
    pre_all<<<TGT_LEN, 256, 65536>>>(preW, preb);
    logits_all<<<NCH * TPAIRS, 256, (16384 + 1536) * 4>>>(emb, outb);
    merge_all<<<TGT_LEN, 256>>>(tgt, emb, outb, out);
    loss_fin<<<1, 32>>>(out, out_size);
}

// round 6
// speedup vs baseline: 4.6528x; 1.1097x over previous
#include <cuda_runtime.h>
#include <math.h>

#define SRC_LEN 400
#define TGT_LEN 100
#define Bsz     32
#define Ed      256
#define Hd      512
#define Vd      32000
#define G3H     1536
#define NB      128      // persistent grid size (<= 148 SMs -> co-resident)
#define NCH     125      // logits v-chunks of 256
#define TQ      4        // timesteps per logits block
#define TGROUPS (TGT_LEN / TQ)   // 25

// ---------------- device scratch --------------------------------------------
__device__ float  g_gi_enc[(size_t)SRC_LEN * G3H * Bsz];
__device__ float  g_gi_dec[(size_t)TGT_LEN * G3H * Bsz];
__device__ float2 g_h2[2][(Hd / 2) * Bsz];
__device__ float2 g_hall[(size_t)TGT_LEN * (Hd / 2) * Bsz];
__device__ float2 g_oeall[(size_t)TGT_LEN * (Ed / 2) * Bsz];
__device__ float  g_pm[(size_t)TGT_LEN * NCH * Bsz];
__device__ float  g_ps[(size_t)TGT_LEN * NCH * Bsz];
__device__ int    g_pi[(size_t)TGT_LEN * NCH * Bsz];
__device__ float  g_loss_t[TGT_LEN];
__device__ unsigned g_bar_enc;
__device__ unsigned g_bar_dec;

// ---------------- f32x2 packed FMA ------------------------------------------
__device__ __forceinline__ float2 ffma2(float2 a, float2 b, float2 c) {
    unsigned long long A = *reinterpret_cast<unsigned long long*>(&a);
    unsigned long long B = *reinterpret_cast<unsigned long long*>(&b);
    unsigned long long C = *reinterpret_cast<unsigned long long*>(&c);
    unsigned long long D;
    asm("fma.rn.f32x2 %0, %1, %2, %3;" : "=l"(D) : "l"(A), "l"(B), "l"(C));
    return *reinterpret_cast<float2*>(&D);
}

// ---------------- grid-wide barrier -----------------------------------------
__device__ __forceinline__ void grid_bar(unsigned* bar, unsigned& target) {
    __threadfence();
    __syncthreads();
    if (threadIdx.x == 0) {
        target += NB;
        atomicAdd(bar, 1u);
        while (*((volatile unsigned*)bar) < target) { }
        __threadfence();
    }
    __syncthreads();
}

__global__ void init_kernel() {
    if (threadIdx.x == 0) { g_bar_enc = 0u; g_bar_dec = 0u; }
}

// ---------------- gi precompute ----------------------------------------------
__global__ void gi_kernel(const int* __restrict__ toks,
                          const float* __restrict__ emb,
                          const float* __restrict__ Wih,
                          const float* __restrict__ bih,
                          int dec_mode) {
    __shared__ float2 xs2[(Ed / 2) * Bsz];
    __shared__ int    tk[Bsz];
    const int t = blockIdx.x, tid = threadIdx.x;

    if (tid < Bsz) {
        int tok;
        if (dec_mode) tok = (t == 0) ? 1 : toks[(t - 1) * Bsz + tid];
        else          tok = toks[t * Bsz + tid];
        tk[tid] = tok;
    }
    __syncthreads();
    {
        const int b = tid & 31, chunk = tid >> 5;
        const float* erow = emb + (size_t)tk[b] * Ed;
        #pragma unroll
        for (int c = 0; c < 8; c++) {
            int e0 = chunk * 32 + c * 4;
            float4 v = *(const float4*)(erow + e0);
            xs2[(e0 >> 1) * Bsz + b]       = make_float2(v.x, v.y);
            xs2[((e0 >> 1) + 1) * Bsz + b] = make_float2(v.z, v.w);
        }
    }
    __syncthreads();

    const int wid = tid >> 5, lane = tid & 31;
    float* out_t = (dec_mode ? g_gi_dec : g_gi_enc) + (size_t)t * G3H * Bsz;

    for (int jt = 0; jt < 24; jt++) {
        const int j0 = wid * 192 + jt * 8;
        float2 acc[8];
        #pragma unroll
        for (int i = 0; i < 8; i++) acc[i] = make_float2(0.f, 0.f);
        #pragma unroll 2
        for (int e = 0; e < Ed; e += 4) {
            const int e2 = e >> 1;
            float2 x01 = xs2[e2 * Bsz + lane];
            float2 x23 = xs2[(e2 + 1) * Bsz + lane];
            const float* wp = Wih + (size_t)j0 * Ed + e;
            #pragma unroll
            for (int jj = 0; jj < 8; jj++) {
                float4 w = *(const float4*)(wp + (size_t)jj * Ed);
                acc[jj] = ffma2(make_float2(w.x, w.y), x01, acc[jj]);
                acc[jj] = ffma2(make_float2(w.z, w.w), x23, acc[jj]);
            }
        }
        #pragma unroll
        for (int jj = 0; jj < 8; jj++)
            out_t[(size_t)(j0 + jj) * Bsz + lane] = acc[jj].x + acc[jj].y + bih[j0 + jj];
    }
}

// ---------------- persistent GRU (512 threads, 8-way k-split) -----------------
#define WS_F   0                        // 12*512 = 6144 floats
#define HP_F   6144                     // 16384 floats
#define PP_F   (6144 + 16384)           // 16*6*32 = 3072 floats
#define REC_SMEM_BYTES ((6144 + 16384 + 3072) * 4)
#define RTHR   512

__device__ __forceinline__ void load_ws(float* ws, const float* __restrict__ Whh, int j0) {
    for (int i = threadIdx.x; i < 12 * 128; i += RTHR) {
        int r = i >> 7, k4 = i & 127;
        int g = r >> 2, jl = r & 3;
        ((float4*)ws)[r * 128 + k4] =
            *(const float4*)&Whh[((size_t)(g * Hd + j0 + jl)) * Hd + k4 * 4];
    }
}

__device__ __forceinline__ void stage_h(float2* hp, const float2* __restrict__ src) {
    const float4* s = (const float4*)src;
    float4* d = (float4*)hp;
    for (int i = threadIdx.x; i < (Hd * Bsz) / 4; i += RTHR) d[i] = __ldcg(s + i);
    __syncthreads();
}

__device__ __forceinline__ void hh_step(const float* __restrict__ ws,
                                        const float2* __restrict__ hp,
                                        const float* __restrict__ gi_t,
                                        const float* __restrict__ bhh,
                                        float2* __restrict__ hout,
                                        float* __restrict__ pp,
                                        int j0) {
    const int tid = threadIdx.x, wid = tid >> 5, lane = tid & 31;
    const int p = wid >> 3, q = wid & 7;       // p: j-pair (0..1), q: k-eighth

    // epilogue warps (q==0) prefetch gate inputs early (hidden by k-loop)
    float pg[6];
    float2 hold = make_float2(0.f, 0.f);
    if (q == 0) {
        const int j = j0 + 2 * p;
        pg[0] = __ldcg(&gi_t[(size_t)(0 * Hd + j) * Bsz + lane]);
        pg[1] = __ldcg(&gi_t[(size_t)(0 * Hd + j + 1) * Bsz + lane]);
        pg[2] = __ldcg(&gi_t[(size_t)(1 * Hd + j) * Bsz + lane]);
        pg[3] = __ldcg(&gi_t[(size_t)(1 * Hd + j + 1) * Bsz + lane]);
        pg[4] = __ldcg(&gi_t[(size_t)(2 * Hd + j) * Bsz + lane]);
        pg[5] = __ldcg(&gi_t[(size_t)(2 * Hd + j + 1) * Bsz + lane]);
        hold  = hp[(j0 / 2 + p) * Bsz + lane];
    }

    float2 acc[6];
    #pragma unroll
    for (int i = 0; i < 6; i++) acc[i] = make_float2(0.f, 0.f);

    const int kbeg = q * 64;
    #pragma unroll 4
    for (int k = kbeg; k < kbeg + 64; k += 4) {
        const int k2 = k >> 1;
        float2 x01 = hp[k2 * Bsz + lane];
        float2 x23 = hp[(k2 + 1) * Bsz + lane];
        #pragma unroll
        for (int g = 0; g < 3; g++) {
            #pragma unroll
            for (int jj = 0; jj < 2; jj++) {
                float4 w = *(const float4*)&ws[(g * 4 + 2 * p + jj) * Hd + k];
                acc[g * 2 + jj] = ffma2(make_float2(w.x, w.y), x01, acc[g * 2 + jj]);
                acc[g * 2 + jj] = ffma2(make_float2(w.z, w.w), x23, acc[g * 2 + jj]);
            }
        }
    }
    #pragma unroll
    for (int i = 0; i < 6; i++)
        pp[((q * 2 + p) * 6 + i) * Bsz + lane] = acc[i].x + acc[i].y;
    __syncthreads();

    if (q == 0) {
        const int fp = p;
        float s[6];
        #pragma unroll
        for (int i = 0; i < 6; i++) {
            float v = 0.f;
            #pragma unroll
            for (int q2 = 0; q2 < 8; q2++) v += pp[((q2 * 2 + fp) * 6 + i) * Bsz + lane];
            s[i] = v;
        }
        float hn[2];
        #pragma unroll
        for (int jj = 0; jj < 2; jj++) {
            int j = j0 + 2 * fp + jj;
            float ghr = s[0 + jj] + bhh[j];
            float ghz = s[2 + jj] + bhh[Hd + j];
            float ghn = s[4 + jj] + bhh[2 * Hd + j];
            float r = 1.0f / (1.0f + expf(-(pg[0 + jj] + ghr)));
            float z = 1.0f / (1.0f + expf(-(pg[2 + jj] + ghz)));
            float n = tanhf(pg[4 + jj] + r * ghn);
            float ho = jj ? hold.y : hold.x;
            hn[jj] = (1.0f - z) * n + z * ho;
        }
        __stcg(&hout[(j0 / 2 + fp) * Bsz + lane], make_float2(hn[0], hn[1]));
    }
}

__global__ void __launch_bounds__(RTHR, 1)
enc_persist(const float* __restrict__ Whh, const float* __restrict__ bhh) {
    extern __shared__ float sm[];
    float*  ws = sm + WS_F;
    float2* hp = (float2*)(sm + HP_F);
    float*  pp = sm + PP_F;
    const int j0 = blockIdx.x * 4;

    load_ws(ws, Whh, j0);
    for (int i = threadIdx.x; i < Hd * Bsz; i += RTHR) ((float*)hp)[i] = 0.f;
    __syncthreads();

    unsigned tgt = 0;
    for (int t = 0; t < SRC_LEN; t++) {
        hh_step(ws, hp, g_gi_enc + (size_t)t * G3H * Bsz, bhh, g_h2[t & 1], pp, j0);
        grid_bar(&g_bar_enc, tgt);
        stage_h(hp, g_h2[t & 1]);
    }
    // final h in g_h2[1]
}

__global__ void __launch_bounds__(RTHR, 1)
dec_rec(const float* __restrict__ Whh, const float* __restrict__ bhh) {
    extern __shared__ float sm[];
    float*  ws = sm + WS_F;
    float2* hp = (float2*)(sm + HP_F);
    float*  pp = sm + PP_F;
    const int j0 = blockIdx.x * 4;

    load_ws(ws, Whh, j0);
    __syncthreads();
    stage_h(hp, g_h2[1]);

    unsigned tc = 0;
    for (int t = 0; t < TGT_LEN; t++) {
        float2* hall_t = &g_hall[(size_t)t * (Hd / 2) * Bsz];
        hh_step(ws, hp, g_gi_dec + (size_t)t * G3H * Bsz, bhh, hall_t, pp, j0);
        grid_bar(&g_bar_dec, tc);
        stage_h(hp, hall_t);
    }
}

// ---------------- decoder phase B: batched pre (oe_all) -----------------------
__global__ void __launch_bounds__(256)
pre_all(const float* __restrict__ preW, const float* __restrict__ preb) {
    extern __shared__ float sm[];
    float2* hs = (float2*)sm;     // 64KB
    const int t = blockIdx.x, tid = threadIdx.x;
    {
        const float4* s4 = (const float4*)&g_hall[(size_t)t * (Hd / 2) * Bsz];
        float4* d4 = (float4*)hs;
        for (int i = tid; i < (Hd * Bsz) / 4; i += 256) d4[i] = __ldg(s4 + i);
        __syncthreads();
    }
    const int wid = tid >> 5, lane = tid & 31;
    for (int grp = 0; grp < 4; grp++) {
        const int e0 = wid * 32 + grp * 8;
        float2 acc[8];
        #pragma unroll
        for (int i = 0; i < 8; i++) acc[i] = make_float2(0.f, 0.f);
        const float* wp = preW + (size_t)e0 * Hd;
        #pragma unroll 2
        for (int k = 0; k < Hd; k += 4) {
            const int k2 = k >> 1;
            float2 x01 = hs[k2 * Bsz + lane];
            float2 x23 = hs[(k2 + 1) * Bsz + lane];
            #pragma unroll
            for (int r = 0; r < 8; r++) {
                float4 w = *(const float4*)(wp + (size_t)r * Hd + k);
                acc[r] = ffma2(make_float2(w.x, w.y), x01, acc[r]);
                acc[r] = ffma2(make_float2(w.z, w.w), x23, acc[r]);
            }
        }
        #pragma unroll
        for (int i = 0; i < 4; i++) {
            float v0 = acc[2 * i].x     + acc[2 * i].y     + preb[e0 + 2 * i];
            float v1 = acc[2 * i + 1].x + acc[2 * i + 1].y + preb[e0 + 2 * i + 1];
            g_oeall[((size_t)t * (Ed / 2) + (e0 >> 1) + i) * Bsz + lane] =
                make_float2(v0, v1);
        }
    }
}

// ---------------- decoder phase C: batched logits, 4 timesteps/block ----------
// grid = NCH * TGROUPS. smem: oes[4][(Ed/2)*Bsz] + merge scratch.
#define LG_SMEM_F (4 * (Ed / 2) * Bsz * 2 + 3 * (TQ * 8 * 32))
__global__ void __launch_bounds__(256, 1)
logits_all(const float* __restrict__ emb, const float* __restrict__ outb) {
    extern __shared__ float sm[];
    float2* oes = (float2*)sm;                   // [4][(Ed/2)*Bsz] float2
    float*  mm  = sm + 4 * (Ed / 2) * Bsz * 2;   // [TQ][8][32]
    float*  ms  = mm + TQ * 8 * 32;
    int*    mi  = (int*)(ms + TQ * 8 * 32);

    const int bid = blockIdx.x;
    const int c = bid / TGROUPS, grp = bid % TGROUPS;
    const int t0 = grp * TQ;
    const int tid = threadIdx.x, wid = tid >> 5, lane = tid & 31;

    {   // stage 4 timesteps of out_emb: 4 * 2048 float4
        const float4* s4 = (const float4*)&g_oeall[(size_t)t0 * (Ed / 2) * Bsz];
        float4* d4 = (float4*)oes;
        for (int i = tid; i < 4 * (Ed * Bsz) / 4; i += 256) d4[i] = __ldg(s4 + i);
        __syncthreads();
    }

    const int base = c * 256 + wid * 32;
    float m[TQ], s[TQ]; int bi[TQ];
    #pragma unroll
    for (int t = 0; t < TQ; t++) { m[t] = -INFINITY; s[t] = 0.f; bi[t] = 0; }

    for (int vt = 0; vt < 4; vt++) {
        const int vb = base + vt * 8;
        float2 acc[TQ][8];
        #pragma unroll
        for (int t = 0; t < TQ; t++)
            #pragma unroll
            for (int i = 0; i < 8; i++) acc[t][i] = make_float2(0.f, 0.f);
        const float* ep = emb + (size_t)vb * Ed;

        for (int e = 0; e < Ed; e += 4) {
            const int e2 = e >> 1;
            float2 x01[TQ], x23[TQ];
            #pragma unroll
            for (int t = 0; t < TQ; t++) {
                x01[t] = oes[t * (Ed / 2) * Bsz + e2 * Bsz + lane];
                x23[t] = oes[t * (Ed / 2) * Bsz + (e2 + 1) * Bsz + lane];
            }
            #pragma unroll
            for (int vv = 0; vv < 8; vv++) {
                float4 w = *(const float4*)(ep + (size_t)vv * Ed + e);
                float2 w01 = make_float2(w.x, w.y), w23 = make_float2(w.z, w.w);
                #pragma unroll
                for (int t = 0; t < TQ; t++) {
                    acc[t][vv] = ffma2(w01, x01[t], acc[t][vv]);
                    acc[t][vv] = ffma2(w23, x23[t], acc[t][vv]);
                }
            }
        }
        #pragma unroll
        for (int vv = 0; vv < 8; vv++) {
            float lb = outb[vb + vv];
            #pragma unroll
            for (int t = 0; t < TQ; t++) {
                float l = acc[t][vv].x + acc[t][vv].y + lb;
                if (l > m[t]) { s[t] = s[t] * __expf(m[t] - l) + 1.0f; m[t] = l; bi[t] = vb + vv; }
                else          { s[t] += __expf(l - m[t]); }
            }
        }
    }
    #pragma unroll
    for (int t = 0; t < TQ; t++) {
        mm[(t * 8 + wid) * 32 + lane] = m[t];
        ms[(t * 8 + wid) * 32 + lane] = s[t];
        mi[(t * 8 + wid) * 32 + lane] = bi[t];
    }
    __syncthreads();

    if (wid < TQ) {
        const int tt = wid;
        float M = mm[(tt * 8 + 0) * 32 + lane];
        float S = ms[(tt * 8 + 0) * 32 + lane];
        int   I = mi[(tt * 8 + 0) * 32 + lane];
        #pragma unroll
        for (int w = 1; w < 8; w++) {
            float m2 = mm[(tt * 8 + w) * 32 + lane];
            float s2 = ms[(tt * 8 + w) * 32 + lane];
            int   i2 = mi[(tt * 8 + w) * 32 + lane];
            if (m2 > M) { S = S * __expf(M - m2) + s2; I = i2; M = m2; }
            else        { S += s2 * __expf(m2 - M); }
        }
        const size_t idx = ((size_t)(t0 + tt) * NCH + c) * 32 + lane;
        g_pm[idx] = M; g_ps[idx] = S; g_pi[idx] = I;
    }
}

// ---------------- decoder phase D: per-t merge, tokens, loss ------------------
__global__ void __launch_bounds__(256)
merge_all(const int* __restrict__ tgt, const float* __restrict__ emb,
          const float* __restrict__ outb, float* __restrict__ dout) {
    __shared__ float smm[8 * 32], sms[8 * 32];
    __shared__ int   smi[8 * 32];
    const int t = blockIdx.x, tid = threadIdx.x, b = tid & 31, cg = tid >> 5;

    float m = -INFINITY, s = 0.f; int bi = 0;
    const int cb = cg * 16, ce = (cb + 16 < NCH) ? cb + 16 : NCH;
    for (int c = cb; c < ce; c++) {
        const size_t idx = ((size_t)t * NCH + c) * 32 + b;
        float m2 = g_pm[idx], s2 = g_ps[idx];
        int   i2 = g_pi[idx];
        if (m2 > m) { s = s * __expf(m - m2) + s2; bi = i2; m = m2; }
        else        { s += s2 * __expf(m2 - m); }
    }
    smm[cg * 32 + b] = m; sms[cg * 32 + b] = s; smi[cg * 32 + b] = bi;
    __syncthreads();

    if (tid < 32) {
        m = smm[tid]; s = sms[tid]; bi = smi[tid];
        #pragma unroll
        for (int c2 = 1; c2 < 8; c2++) {
            float m2 = smm[c2 * 32 + tid];
            float s2 = sms[c2 * 32 + tid];
            int   i2 = smi[c2 * 32 + tid];
            if (m2 > m) { s = s * __expf(m - m2) + s2; bi = i2; m = m2; }
            else        { s += s2 * __expf(m2 - m); }
        }
        int gold = tgt[t * Bsz + tid];
        float2 acc = make_float2(0.f, 0.f);
        const float* grow = emb + (size_t)gold * Ed;
        #pragma unroll 4
        for (int e = 0; e < Ed; e += 4) {
            float4 w = *(const float4*)(grow + e);
            float2 o01 = g_oeall[((size_t)t * (Ed / 2) + (e >> 1)) * Bsz + tid];
            float2 o23 = g_oeall[((size_t)t * (Ed / 2) + (e >> 1) + 1) * Bsz + tid];
            acc = ffma2(make_float2(w.x, w.y), o01, acc);
            acc = ffma2(make_float2(w.z, w.w), o23, acc);
        }
        float lg = acc.x + acc.y + outb[gold];
        float prob = expf(lg - m) / s;
        float nll = -logf(prob + 1e-20f);
        float maskf = (gold != 0) ? 1.0f : 0.0f;
        float num = nll * maskf, den = maskf;
        #pragma unroll
        for (int o = 16; o > 0; o >>= 1) {
            num += __shfl_down_sync(0xffffffffu, num, o);
            den += __shfl_down_sync(0xffffffffu, den, o);
        }
        dout[t * Bsz + tid] = (float)bi;
        if (tid == 0) g_loss_t[t] = num / fmaxf(den, 1.0f);
    }
}

__global__ void loss_fin(float* __restrict__ dout, int out_size) {
    if (out_size <= TGT_LEN * Bsz) return;
    const int lane = threadIdx.x;
    float s = 0.f;
    for (int t = lane; t < TGT_LEN; t += 32) s += g_loss_t[t];
    #pragma unroll
    for (int o = 16; o > 0; o >>= 1) s += __shfl_down_sync(0xffffffffu, s, o);
    if (lane == 0) dout[TGT_LEN * Bsz] = s;
}

// ---------------- launch ------------------------------------------------------
extern "C" void kernel_launch(void* const* d_in, const int* in_sizes, int n_in,
                              void* d_out, int out_size) {
    const int*   src  = (const int*)  d_in[0];
    const int*   tgt  = (const int*)  d_in[1];
    const float* emb  = (const float*)d_in[2];
    const float* eWih = (const float*)d_in[3];
    const float* eWhh = (const float*)d_in[4];
    const float* ebih = (const float*)d_in[5];
    const float* ebhh = (const float*)d_in[6];
    const float* dWih = (const float*)d_in[7];
    const float* dWhh = (const float*)d_in[8];
    const float* dbih = (const float*)d_in[9];
    const float* dbhh = (const float*)d_in[10];
    const float* preW = (const float*)d_in[11];
    const float* preb = (const float*)d_in[12];
    const float* outb = (const float*)d_in[13];
    float* out = (float*)d_out;

    static int attr_done = 0;
    if (!attr_done) {
        cudaFuncSetAttribute(enc_persist, cudaFuncAttributeMaxDynamicSharedMemorySize,
                             REC_SMEM_BYTES);
        cudaFuncSetAttribute(dec_rec, cudaFuncAttributeMaxDynamicSharedMemorySize,
                             REC_SMEM_BYTES);
        cudaFuncSetAttribute(pre_all, cudaFuncAttributeMaxDynamicSharedMemorySize,
                             65536);
        cudaFuncSetAttribute(logits_all, cudaFuncAttributeMaxDynamicSharedMemorySize,
                             LG_SMEM_F * 4);
        attr_done = 1;
    }

    init_kernel<<<1, 32>>>();
    gi_kernel<<<SRC_LEN, 256>>>(src, emb, eWih, ebih, 0);
    gi_kernel<<<TGT_LEN, 256>>>(tgt, emb, dWih, dbih, 1);
    enc_persist<<<NB, RTHR, REC_SMEM_BYTES>>>(eWhh, ebhh);
    dec_rec<<<NB, RTHR, REC_SMEM_BYTES>>>(dWhh, dbhh);
    pre_all<<<TGT_LEN, 256, 65536>>>(preW, preb);
    logits_all<<<NCH * TGROUPS, 256, LG_SMEM_F * 4>>>(emb, outb);
    merge_all<<<TGT_LEN, 256>>>(tgt, emb, outb, out);
    loss_fin<<<1, 32>>>(out, out_size);
}

// round 7
// speedup vs baseline: 4.9672x; 1.0676x over previous
#include <cuda_runtime.h>
#include <math.h>

#define SRC_LEN 400
#define TGT_LEN 100
#define Bsz     32
#define Ed      256
#define Hd      512
#define Vd      32000
#define G3H     1536
#define NB      128      // persistent grid size (<= 148 SMs -> co-resident)
#define NCH     125      // logits v-chunks of 256
#define TQ      4        // timesteps per logits block
#define TGROUPS (TGT_LEN / TQ)   // 25
#define RTHR    512

// ---------------- device scratch --------------------------------------------
__device__ float  g_gi_enc[(size_t)SRC_LEN * G3H * Bsz];
__device__ float  g_gi_dec[(size_t)TGT_LEN * G3H * Bsz];
__device__ float2 g_h2[2][(Hd / 2) * Bsz];
__device__ float2 g_hall[(size_t)TGT_LEN * (Hd / 2) * Bsz];
__device__ float2 g_oeall[(size_t)TGT_LEN * (Ed / 2) * Bsz];
__device__ float  g_pm[(size_t)TGT_LEN * NCH * Bsz];
__device__ float  g_ps[(size_t)TGT_LEN * NCH * Bsz];
__device__ int    g_pi[(size_t)TGT_LEN * NCH * Bsz];
__device__ float  g_loss_t[TGT_LEN];
__device__ unsigned g_bar_enc;
__device__ unsigned g_bar_dec;

// ---------------- f32x2 packed FMA ------------------------------------------
__device__ __forceinline__ float2 ffma2(float2 a, float2 b, float2 c) {
    unsigned long long A = *reinterpret_cast<unsigned long long*>(&a);
    unsigned long long B = *reinterpret_cast<unsigned long long*>(&b);
    unsigned long long C = *reinterpret_cast<unsigned long long*>(&c);
    unsigned long long D;
    asm("fma.rn.f32x2 %0, %1, %2, %3;" : "=l"(D) : "l"(A), "l"(B), "l"(C));
    return *reinterpret_cast<float2*>(&D);
}

// ---------------- grid-wide barrier (CG-style release/acquire) ---------------
__device__ __forceinline__ void grid_bar(unsigned* bar, unsigned& target) {
    __syncthreads();
    if (threadIdx.x == 0) {
        target += NB;
        asm volatile("red.release.gpu.global.add.u32 [%0], %1;"
                     :: "l"(bar), "r"(1u) : "memory");
        unsigned v;
        do {
            asm volatile("ld.acquire.gpu.global.u32 %0, [%1];"
                         : "=r"(v) : "l"(bar) : "memory");
        } while (v < target);
    }
    __syncthreads();
}

__global__ void init_kernel() {
    int i = blockIdx.x * blockDim.x + threadIdx.x;
    if (i < Hd * Bsz) ((float*)g_h2[0])[i] = 0.0f;   // encoder h0 = 0
    if (i == 0) { g_bar_enc = 0u; g_bar_dec = 0u; }
}

// ---------------- gi precompute ----------------------------------------------
__global__ void gi_kernel(const int* __restrict__ toks,
                          const float* __restrict__ emb,
                          const float* __restrict__ Wih,
                          const float* __restrict__ bih,
                          int dec_mode) {
    __shared__ float2 xs2[(Ed / 2) * Bsz];
    __shared__ int    tk[Bsz];
    const int t = blockIdx.x, tid = threadIdx.x;

    if (tid < Bsz) {
        int tok;
        if (dec_mode) tok = (t == 0) ? 1 : toks[(t - 1) * Bsz + tid];
        else          tok = toks[t * Bsz + tid];
        tk[tid] = tok;
    }
    __syncthreads();
    {
        const int b = tid & 31, chunk = tid >> 5;
        const float* erow = emb + (size_t)tk[b] * Ed;
        #pragma unroll
        for (int c = 0; c < 8; c++) {
            int e0 = chunk * 32 + c * 4;
            float4 v = *(const float4*)(erow + e0);
            xs2[(e0 >> 1) * Bsz + b]       = make_float2(v.x, v.y);
            xs2[((e0 >> 1) + 1) * Bsz + b] = make_float2(v.z, v.w);
        }
    }
    __syncthreads();

    const int wid = tid >> 5, lane = tid & 31;
    float* out_t = (dec_mode ? g_gi_dec : g_gi_enc) + (size_t)t * G3H * Bsz;

    for (int jt = 0; jt < 24; jt++) {
        const int j0 = wid * 192 + jt * 8;
        float2 acc[8];
        #pragma unroll
        for (int i = 0; i < 8; i++) acc[i] = make_float2(0.f, 0.f);
        #pragma unroll 2
        for (int e = 0; e < Ed; e += 4) {
            const int e2 = e >> 1;
            float2 x01 = xs2[e2 * Bsz + lane];
            float2 x23 = xs2[(e2 + 1) * Bsz + lane];
            const float* wp = Wih + (size_t)j0 * Ed + e;
            #pragma unroll
            for (int jj = 0; jj < 8; jj++) {
                float4 w = *(const float4*)(wp + (size_t)jj * Ed);
                acc[jj] = ffma2(make_float2(w.x, w.y), x01, acc[jj]);
                acc[jj] = ffma2(make_float2(w.z, w.w), x23, acc[jj]);
            }
        }
        #pragma unroll
        for (int jj = 0; jj < 8; jj++)
            out_t[(size_t)(j0 + jj) * Bsz + lane] = acc[jj].x + acc[jj].y + bih[j0 + jj];
    }
}

// ---------------- persistent GRU: 16-way k-split, h direct from L2 -----------
// smem: ws[12][512] (24KB) + pp[16][12][32] (24KB) = 48KB
#define WS_F   0
#define PP_F   6144
#define REC_SMEM_BYTES ((6144 + 6144) * 4)

__device__ __forceinline__ void load_ws(float* ws, const float* __restrict__ Whh, int j0) {
    for (int i = threadIdx.x; i < 12 * 128; i += RTHR) {
        int r = i >> 7, k4 = i & 127;
        int g = r >> 2, jl = r & 3;
        ((float4*)ws)[r * 128 + k4] =
            *(const float4*)&Whh[((size_t)(g * Hd + j0 + jl)) * Hd + k4 * 4];
    }
}

// one GRU step. hprev: GLOBAL h layout [k/2][b] float2. hout: global same layout.
__device__ __forceinline__ void hh_step(const float* __restrict__ ws,
                                        const float2* __restrict__ hprev,
                                        const float* __restrict__ gi_t,
                                        const float* __restrict__ bhh,
                                        float2* __restrict__ hout,
                                        float* __restrict__ pp,
                                        int j0) {
    const int tid = threadIdx.x, wid = tid >> 5, lane = tid & 31;

    // epilogue warps prefetch gate inputs + old h early (latency hidden by k-loop)
    float pg[6];
    float2 hold = make_float2(0.f, 0.f);
    if (wid < 2) {
        const int j = j0 + 2 * wid;
        pg[0] = __ldcg(&gi_t[(size_t)(0 * Hd + j) * Bsz + lane]);
        pg[1] = __ldcg(&gi_t[(size_t)(0 * Hd + j + 1) * Bsz + lane]);
        pg[2] = __ldcg(&gi_t[(size_t)(1 * Hd + j) * Bsz + lane]);
        pg[3] = __ldcg(&gi_t[(size_t)(1 * Hd + j + 1) * Bsz + lane]);
        pg[4] = __ldcg(&gi_t[(size_t)(2 * Hd + j) * Bsz + lane]);
        pg[5] = __ldcg(&gi_t[(size_t)(2 * Hd + j + 1) * Bsz + lane]);
        hold  = __ldcg(&hprev[(j0 / 2 + wid) * Bsz + lane]);
    }

    float2 acc[12];
    #pragma unroll
    for (int i = 0; i < 12; i++) acc[i] = make_float2(0.f, 0.f);

    const int kbeg = wid * 32;                     // each warp: 32-k slice
    #pragma unroll
    for (int k = kbeg; k < kbeg + 32; k += 4) {
        const int k2 = k >> 1;
        float2 x01 = __ldcg(&hprev[k2 * Bsz + lane]);
        float2 x23 = __ldcg(&hprev[(k2 + 1) * Bsz + lane]);
        #pragma unroll
        for (int r = 0; r < 12; r++) {
            float4 w = *(const float4*)&ws[r * Hd + k];
            acc[r] = ffma2(make_float2(w.x, w.y), x01, acc[r]);
            acc[r] = ffma2(make_float2(w.z, w.w), x23, acc[r]);
        }
    }
    #pragma unroll
    for (int r = 0; r < 12; r++)
        pp[(wid * 12 + r) * 32 + lane] = acc[r].x + acc[r].y;
    __syncthreads();

    if (wid < 2) {
        const int e = wid;
        float s[6];
        #pragma unroll
        for (int g = 0; g < 3; g++) {
            #pragma unroll
            for (int jj = 0; jj < 2; jj++) {
                const int row = g * 4 + 2 * e + jj;
                float v = 0.f;
                #pragma unroll
                for (int w = 0; w < 16; w++) v += pp[(w * 12 + row) * 32 + lane];
                s[g * 2 + jj] = v;
            }
        }
        float hn[2];
        #pragma unroll
        for (int jj = 0; jj < 2; jj++) {
            int j = j0 + 2 * e + jj;
            float ghr = s[0 + jj] + bhh[j];
            float ghz = s[2 + jj] + bhh[Hd + j];
            float ghn = s[4 + jj] + bhh[2 * Hd + j];
            float r = 1.0f / (1.0f + expf(-(pg[0 + jj] + ghr)));
            float z = 1.0f / (1.0f + expf(-(pg[2 + jj] + ghz)));
            float n = tanhf(pg[4 + jj] + r * ghn);
            float ho = jj ? hold.y : hold.x;
            hn[jj] = (1.0f - z) * n + z * ho;
        }
        __stcg(&hout[(j0 / 2 + e) * Bsz + lane], make_float2(hn[0], hn[1]));
    }
}

__global__ void __launch_bounds__(RTHR, 1)
enc_persist(const float* __restrict__ Whh, const float* __restrict__ bhh) {
    extern __shared__ float sm[];
    float* ws = sm + WS_F;
    float* pp = sm + PP_F;
    const int j0 = blockIdx.x * 4;

    load_ws(ws, Whh, j0);
    __syncthreads();

    unsigned tgt = 0;
    for (int t = 0; t < SRC_LEN; t++) {
        const float2* hprev = g_h2[t & 1];
        float2* hnew = g_h2[(t & 1) ^ 1];
        hh_step(ws, hprev, g_gi_enc + (size_t)t * G3H * Bsz, bhh, hnew, pp, j0);
        grid_bar(&g_bar_enc, tgt);
    }
    // SRC_LEN=400 even -> final h in g_h2[0]
}

__global__ void __launch_bounds__(RTHR, 1)
dec_rec(const float* __restrict__ Whh, const float* __restrict__ bhh) {
    extern __shared__ float sm[];
    float* ws = sm + WS_F;
    float* pp = sm + PP_F;
    const int j0 = blockIdx.x * 4;

    load_ws(ws, Whh, j0);
    __syncthreads();

    unsigned tc = 0;
    for (int t = 0; t < TGT_LEN; t++) {
        const float2* hprev = (t == 0) ? g_h2[0]
                                       : &g_hall[(size_t)(t - 1) * (Hd / 2) * Bsz];
        hh_step(ws, hprev, g_gi_dec + (size_t)t * G3H * Bsz, bhh,
                &g_hall[(size_t)t * (Hd / 2) * Bsz], pp, j0);
        grid_bar(&g_bar_dec, tc);
    }
}

// ---------------- decoder phase B: batched pre (oe_all) -----------------------
__global__ void __launch_bounds__(256)
pre_all(const float* __restrict__ preW, const float* __restrict__ preb) {
    extern __shared__ float sm[];
    float2* hs = (float2*)sm;     // 64KB
    const int t = blockIdx.x, tid = threadIdx.x;
    {
        const float4* s4 = (const float4*)&g_hall[(size_t)t * (Hd / 2) * Bsz];
        float4* d4 = (float4*)hs;
        for (int i = tid; i < (Hd * Bsz) / 4; i += 256) d4[i] = __ldg(s4 + i);
        __syncthreads();
    }
    const int wid = tid >> 5, lane = tid & 31;
    for (int grp = 0; grp < 4; grp++) {
        const int e0 = wid * 32 + grp * 8;
        float2 acc[8];
        #pragma unroll
        for (int i = 0; i < 8; i++) acc[i] = make_float2(0.f, 0.f);
        const float* wp = preW + (size_t)e0 * Hd;
        #pragma unroll 2
        for (int k = 0; k < Hd; k += 4) {
            const int k2 = k >> 1;
            float2 x01 = hs[k2 * Bsz + lane];
            float2 x23 = hs[(k2 + 1) * Bsz + lane];
            #pragma unroll
            for (int r = 0; r < 8; r++) {
                float4 w = *(const float4*)(wp + (size_t)r * Hd + k);
                acc[r] = ffma2(make_float2(w.x, w.y), x01, acc[r]);
                acc[r] = ffma2(make_float2(w.z, w.w), x23, acc[r]);
            }
        }
        #pragma unroll
        for (int i = 0; i < 4; i++) {
            float v0 = acc[2 * i].x     + acc[2 * i].y     + preb[e0 + 2 * i];
            float v1 = acc[2 * i + 1].x + acc[2 * i + 1].y + preb[e0 + 2 * i + 1];
            g_oeall[((size_t)t * (Ed / 2) + (e0 >> 1) + i) * Bsz + lane] =
                make_float2(v0, v1);
        }
    }
}

// ---------------- decoder phase C: batched logits, 4 timesteps/block ----------
#define LG_SMEM_F (4 * (Ed / 2) * Bsz * 2 + 3 * (TQ * 8 * 32))
__global__ void __launch_bounds__(256, 1)
logits_all(const float* __restrict__ emb, const float* __restrict__ outb) {
    extern __shared__ float sm[];
    float2* oes = (float2*)sm;
    float*  mm  = sm + 4 * (Ed / 2) * Bsz * 2;
    float*  ms  = mm + TQ * 8 * 32;
    int*    mi  = (int*)(ms + TQ * 8 * 32);

    const int bid = blockIdx.x;
    const int c = bid / TGROUPS, grp = bid % TGROUPS;
    const int t0 = grp * TQ;
    const int tid = threadIdx.x, wid = tid >> 5, lane = tid & 31;

    {
        const float4* s4 = (const float4*)&g_oeall[(size_t)t0 * (Ed / 2) * Bsz];
        float4* d4 = (float4*)oes;
        for (int i = tid; i < 4 * (Ed * Bsz) / 4; i += 256) d4[i] = __ldg(s4 + i);
        __syncthreads();
    }

    const int base = c * 256 + wid * 32;
    float m[TQ], s[TQ]; int bi[TQ];
    #pragma unroll
    for (int t = 0; t < TQ; t++) { m[t] = -INFINITY; s[t] = 0.f; bi[t] = 0; }

    for (int vt = 0; vt < 4; vt++) {
        const int vb = base + vt * 8;
        float2 acc[TQ][8];
        #pragma unroll
        for (int t = 0; t < TQ; t++)
            #pragma unroll
            for (int i = 0; i < 8; i++) acc[t][i] = make_float2(0.f, 0.f);
        const float* ep = emb + (size_t)vb * Ed;

        for (int e = 0; e < Ed; e += 4) {
            const int e2 = e >> 1;
            float2 x01[TQ], x23[TQ];
            #pragma unroll
            for (int t = 0; t < TQ; t++) {
                x01[t] = oes[t * (Ed / 2) * Bsz + e2 * Bsz + lane];
                x23[t] = oes[t * (Ed / 2) * Bsz + (e2 + 1) * Bsz + lane];
            }
            #pragma unroll
            for (int vv = 0; vv < 8; vv++) {
                float4 w = *(const float4*)(ep + (size_t)vv * Ed + e);
                float2 w01 = make_float2(w.x, w.y), w23 = make_float2(w.z, w.w);
                #pragma unroll
                for (int t = 0; t < TQ; t++) {
                    acc[t][vv] = ffma2(w01, x01[t], acc[t][vv]);
                    acc[t][vv] = ffma2(w23, x23[t], acc[t][vv]);
                }
            }
        }
        #pragma unroll
        for (int vv = 0; vv < 8; vv++) {
            float lb = outb[vb + vv];
            #pragma unroll
            for (int t = 0; t < TQ; t++) {
                float l = acc[t][vv].x + acc[t][vv].y + lb;
                if (l > m[t]) { s[t] = s[t] * __expf(m[t] - l) + 1.0f; m[t] = l; bi[t] = vb + vv; }
                else          { s[t] += __expf(l - m[t]); }
            }
        }
    }
    #pragma unroll
    for (int t = 0; t < TQ; t++) {
        mm[(t * 8 + wid) * 32 + lane] = m[t];
        ms[(t * 8 + wid) * 32 + lane] = s[t];
        mi[(t * 8 + wid) * 32 + lane] = bi[t];
    }
    __syncthreads();

    if (wid < TQ) {
        const int tt = wid;
        float M = mm[(tt * 8 + 0) * 32 + lane];
        float S = ms[(tt * 8 + 0) * 32 + lane];
        int   I = mi[(tt * 8 + 0) * 32 + lane];
        #pragma unroll
        for (int w = 1; w < 8; w++) {
            float m2 = mm[(tt * 8 + w) * 32 + lane];
            float s2 = ms[(tt * 8 + w) * 32 + lane];
            int   i2 = mi[(tt * 8 + w) * 32 + lane];
            if (m2 > M) { S = S * __expf(M - m2) + s2; I = i2; M = m2; }
            else        { S += s2 * __expf(m2 - M); }
        }
        const size_t idx = ((size_t)(t0 + tt) * NCH + c) * 32 + lane;
        g_pm[idx] = M; g_ps[idx] = S; g_pi[idx] = I;
    }
}

// ---------------- decoder phase D: per-t merge, tokens, loss ------------------
__global__ void __launch_bounds__(256)
merge_all(const int* __restrict__ tgt, const float* __restrict__ emb,
          const float* __restrict__ outb, float* __restrict__ dout) {
    __shared__ float smm[8 * 32], sms[8 * 32];
    __shared__ int   smi[8 * 32];
    const int t = blockIdx.x, tid = threadIdx.x, b = tid & 31, cg = tid >> 5;

    float m = -INFINITY, s = 0.f; int bi = 0;
    const int cb = cg * 16, ce = (cb + 16 < NCH) ? cb + 16 : NCH;
    for (int c = cb; c < ce; c++) {
        const size_t idx = ((size_t)t * NCH + c) * 32 + b;
        float m2 = g_pm[idx], s2 = g_ps[idx];
        int   i2 = g_pi[idx];
        if (m2 > m) { s = s * __expf(m - m2) + s2; bi = i2; m = m2; }
        else        { s += s2 * __expf(m2 - m); }
    }
    smm[cg * 32 + b] = m; sms[cg * 32 + b] = s; smi[cg * 32 + b] = bi;
    __syncthreads();

    if (tid < 32) {
        m = smm[tid]; s = sms[tid]; bi = smi[tid];
        #pragma unroll
        for (int c2 = 1; c2 < 8; c2++) {
            float m2 = smm[c2 * 32 + tid];
            float s2 = sms[c2 * 32 + tid];
            int   i2 = smi[c2 * 32 + tid];
            if (m2 > m) { s = s * __expf(m - m2) + s2; bi = i2; m = m2; }
            else        { s += s2 * __expf(m2 - m); }
        }
        int gold = tgt[t * Bsz + tid];
        float2 acc = make_float2(0.f, 0.f);
        const float* grow = emb + (size_t)gold * Ed;
        #pragma unroll 4
        for (int e = 0; e < Ed; e += 4) {
            float4 w = *(const float4*)(grow + e);
            float2 o01 = g_oeall[((size_t)t * (Ed / 2) + (e >> 1)) * Bsz + tid];
            float2 o23 = g_oeall[((size_t)t * (Ed / 2) + (e >> 1) + 1) * Bsz + tid];
            acc = ffma2(make_float2(w.x, w.y), o01, acc);
            acc = ffma2(make_float2(w.z, w.w), o23, acc);
        }
        float lg = acc.x + acc.y + outb[gold];
        float prob = expf(lg - m) / s;
        float nll = -logf(prob + 1e-20f);
        float maskf = (gold != 0) ? 1.0f : 0.0f;
        float num = nll * maskf, den = maskf;
        #pragma unroll
        for (int o = 16; o > 0; o >>= 1) {
            num += __shfl_down_sync(0xffffffffu, num, o);
            den += __shfl_down_sync(0xffffffffu, den, o);
        }
        dout[t * Bsz + tid] = (float)bi;
        if (tid == 0) g_loss_t[t] = num / fmaxf(den, 1.0f);
    }
}

__global__ void loss_fin(float* __restrict__ dout, int out_size) {
    if (out_size <= TGT_LEN * Bsz) return;
    const int lane = threadIdx.x;
    float s = 0.f;
    for (int t = lane; t < TGT_LEN; t += 32) s += g_loss_t[t];
    #pragma unroll
    for (int o = 16; o > 0; o >>= 1) s += __shfl_down_sync(0xffffffffu, s, o);
    if (lane == 0) dout[TGT_LEN * Bsz] = s;
}

// ---------------- launch ------------------------------------------------------
extern "C" void kernel_launch(void* const* d_in, const int* in_sizes, int n_in,
                              void* d_out, int out_size) {
    const int*   src  = (const int*)  d_in[0];
    const int*   tgt  = (const int*)  d_in[1];
    const float* emb  = (const float*)d_in[2];
    const float* eWih = (const float*)d_in[3];
    const float* eWhh = (const float*)d_in[4];
    const float* ebih = (const float*)d_in[5];
    const float* ebhh = (const float*)d_in[6];
    const float* dWih = (const float*)d_in[7];
    const float* dWhh = (const float*)d_in[8];
    const float* dbih = (const float*)d_in[9];
    const float* dbhh = (const float*)d_in[10];
    const float* preW = (const float*)d_in[11];
    const float* preb = (const float*)d_in[12];
    const float* outb = (const float*)d_in[13];
    float* out = (float*)d_out;

    static int attr_done = 0;
    if (!attr_done) {
        cudaFuncSetAttribute(enc_persist, cudaFuncAttributeMaxDynamicSharedMemorySize,
                             REC_SMEM_BYTES);
        cudaFuncSetAttribute(dec_rec, cudaFuncAttributeMaxDynamicSharedMemorySize,
                             REC_SMEM_BYTES);
        cudaFuncSetAttribute(pre_all, cudaFuncAttributeMaxDynamicSharedMemorySize,
                             65536);
        cudaFuncSetAttribute(logits_all, cudaFuncAttributeMaxDynamicSharedMemorySize,
                             LG_SMEM_F * 4);
        attr_done = 1;
    }

    init_kernel<<<64, 256>>>();
    gi_kernel<<<SRC_LEN, 256>>>(src, emb, eWih, ebih, 0);
    gi_kernel<<<TGT_LEN, 256>>>(tgt, emb, dWih, dbih, 1);
    enc_persist<<<NB, RTHR, REC_SMEM_BYTES>>>(eWhh, ebhh);
    dec_rec<<<NB, RTHR, REC_SMEM_BYTES>>>(dWhh, dbhh);
    pre_all<<<TGT_LEN, 256, 65536>>>(preW, preb);
    logits_all<<<NCH * TGROUPS, 256, LG_SMEM_F * 4>>>(emb, outb);
    merge_all<<<TGT_LEN, 256>>>(tgt, emb, outb, out);
    loss_fin<<<1, 32>>>(out, out_size);
}